// round 8
// baseline (speedup 1.0000x reference)
#include <cuda_runtime.h>

#define NL 4
#define NNODE 50000
#define NEDGE 800000
#define FDIM 256

// ---------------- scratch (static device globals; no allocation allowed) ----
__device__ float    g_etmp[(size_t)NEDGE * FDIM];       // e_tmp  [E,F]
__device__ float    g_hw[(size_t)5 * NNODE * FDIM];     // hWs,hWd,hWf,hWb,h_tmp
__device__ float    g_logf[NEDGE];
__device__ float    g_logb[NEDGE];
__device__ int      g_degf[NNODE], g_degb[NNODE];
__device__ int      g_rpf[NNODE + 1], g_rpb[NNODE + 1];
__device__ int      g_curf[NNODE], g_curb[NNODE];
__device__ int      g_eidf[NEDGE], g_eidb[NEDGE];
__device__ float    g_sum[FDIM], g_ssq[FDIM], g_mean[FDIM], g_rstd[FDIM];
__device__ float    g_sume[FDIM], g_ssqe[FDIM], g_meane[FDIM], g_rstde[FDIM];

// ---------------- helpers ----------------------------------------------------
__device__ __forceinline__ float ftf32(float x) {
    asm("cvt.rna.tf32.f32 %0, %0;" : "+f"(x));
    return x;
}
__device__ __forceinline__ void mma8(float* c, const unsigned* a, const unsigned* b) {
    asm volatile(
        "mma.sync.aligned.m16n8k8.row.col.f32.tf32.tf32.f32 "
        "{%0,%1,%2,%3}, {%4,%5,%6,%7}, {%8,%9}, {%0,%1,%2,%3};"
        : "+f"(c[0]), "+f"(c[1]), "+f"(c[2]), "+f"(c[3])
        : "r"(a[0]), "r"(a[1]), "r"(a[2]), "r"(a[3]), "r"(b[0]), "r"(b[1]));
}

// ================= node GEMM: 128x128 tile, batched over 5 weights ===========
#define BM 128
#define BK 16
#define APAD 20
#define BPAD 136

struct NodeGemmParams { const float* W[5]; float* C[5]; };

__global__ __launch_bounds__(256)
void tgemm_node(const float* __restrict__ A, NodeGemmParams p, int M)
{
    const float* __restrict__ W = p.W[blockIdx.z];
    float* __restrict__ C = p.C[blockIdx.z];

    __shared__ __align__(16) float As[2][BM][APAD];
    __shared__ __align__(16) float Bs[2][BK][BPAD];

    const int tid  = threadIdx.x;
    const int warp = tid >> 5;
    const int lane = tid & 31;
    const int wm   = warp & 3;
    const int wn   = warp >> 2;
    const int bm   = blockIdx.x * BM;
    const int bn   = blockIdx.y * 128;
    const int g    = lane >> 2;
    const int tg   = lane & 3;

    const int ar0 = tid >> 2;
    const int ac  = (tid & 3) * 4;
    const int br0 = tid >> 5;
    const int bc0 = (tid & 31) * 4;

    float acc[2][8][4];
#pragma unroll
    for (int i = 0; i < 2; i++)
#pragma unroll
        for (int j = 0; j < 8; j++)
#pragma unroll
            for (int q = 0; q < 4; q++) acc[i][j][q] = 0.f;

    float4 av[2], bv[2];

    auto gload = [&](int k0) {
        const float4 z = make_float4(0.f, 0.f, 0.f, 0.f);
        int r0 = bm + ar0, r1 = bm + ar0 + 64;
        av[0] = (r0 < M) ? *(const float4*)(A + (size_t)r0 * 256 + k0 + ac) : z;
        av[1] = (r1 < M) ? *(const float4*)(A + (size_t)r1 * 256 + k0 + ac) : z;
        bv[0] = *(const float4*)(W + (size_t)(k0 + br0) * 256 + bn + bc0);
        bv[1] = *(const float4*)(W + (size_t)(k0 + br0 + 8) * 256 + bn + bc0);
    };
    auto sstore = [&](int s) {
        float4 v;
        v = av[0]; v.x = ftf32(v.x); v.y = ftf32(v.y); v.z = ftf32(v.z); v.w = ftf32(v.w);
        *(float4*)(&As[s][ar0][ac]) = v;
        v = av[1]; v.x = ftf32(v.x); v.y = ftf32(v.y); v.z = ftf32(v.z); v.w = ftf32(v.w);
        *(float4*)(&As[s][ar0 + 64][ac]) = v;
        v = bv[0]; v.x = ftf32(v.x); v.y = ftf32(v.y); v.z = ftf32(v.z); v.w = ftf32(v.w);
        *(float4*)(&Bs[s][br0][bc0]) = v;
        v = bv[1]; v.x = ftf32(v.x); v.y = ftf32(v.y); v.z = ftf32(v.z); v.w = ftf32(v.w);
        *(float4*)(&Bs[s][br0 + 8][bc0]) = v;
    };

    gload(0);
    sstore(0);
    __syncthreads();

#pragma unroll 2
    for (int kt = 0; kt < 16; kt++) {
        const int cur = kt & 1;
        if (kt < 15) gload((kt + 1) * BK);

#pragma unroll
        for (int ks = 0; ks < 2; ks++) {
            const int k = ks * 8;
            unsigned af_[2][4];
#pragma unroll
            for (int mt = 0; mt < 2; mt++) {
                const int rb = wm * 32 + mt * 16;
                af_[mt][0] = __float_as_uint(As[cur][rb + g][k + tg]);
                af_[mt][1] = __float_as_uint(As[cur][rb + g + 8][k + tg]);
                af_[mt][2] = __float_as_uint(As[cur][rb + g][k + tg + 4]);
                af_[mt][3] = __float_as_uint(As[cur][rb + g + 8][k + tg + 4]);
            }
            unsigned bf[8][2];
#pragma unroll
            for (int nt = 0; nt < 8; nt++) {
                const int n = wn * 64 + nt * 8 + g;
                bf[nt][0] = __float_as_uint(Bs[cur][k + tg][n]);
                bf[nt][1] = __float_as_uint(Bs[cur][k + tg + 4][n]);
            }
#pragma unroll
            for (int mt = 0; mt < 2; mt++)
#pragma unroll
                for (int nt = 0; nt < 8; nt++)
                    mma8(acc[mt][nt], af_[mt], bf[nt]);
        }

        if (kt < 15) sstore((kt + 1) & 1);
        __syncthreads();
    }

#pragma unroll
    for (int mt = 0; mt < 2; mt++) {
#pragma unroll
        for (int rr = 0; rr < 2; rr++) {
            const int r = bm + wm * 32 + mt * 16 + rr * 8 + g;
            if (r < M) {
#pragma unroll
                for (int nt = 0; nt < 8; nt++) {
                    const int col = bn + wn * 64 + nt * 8 + tg * 2;
                    *(float2*)(C + (size_t)r * 256 + col) =
                        make_float2(acc[mt][nt][rr * 2], acc[mt][nt][rr * 2 + 1]);
                }
            }
        }
    }
}

// ================= edge GEMM: 64x256 tile, grid.y=1, fully fused =============
// Prologue (fuse=1): A-row = ebase + relu(bn(etmp_old)), written to eout.
// Epilogue: etmp_new = A@W + G0[src] + G1[dst]; also exact attention logits
//           (leaky applied) and BN column sums/ssq.
#define EBM 64
#define EBK 16
#define EAPAD 20
#define EBPAD 264

__global__ __launch_bounds__(256)
void tgemm_edge_f(const float* __restrict__ ebase,
                  float* __restrict__ etmp,            // in: etmp_old, out: etmp_new
                  float* __restrict__ eout,
                  const float* __restrict__ W,
                  const float* __restrict__ G0, const float* __restrict__ G1,
                  const int* __restrict__ src, const int* __restrict__ dst,
                  const float* __restrict__ meane, const float* __restrict__ rstde,
                  const float* __restrict__ gam, const float* __restrict__ bet,
                  const float* __restrict__ attf, const float* __restrict__ attb,
                  float* __restrict__ logf, float* __restrict__ logb,
                  float* __restrict__ sume, float* __restrict__ ssqe,
                  int fuse)
{
    __shared__ __align__(16) float As[2][EBM][EAPAD];
    __shared__ __align__(16) float Bs[2][EBK][EBPAD];
    __shared__ float s_cs[256], s_cq[256];
    __shared__ float s_dotf[EBM], s_dotb[EBM];

    const int tid  = threadIdx.x;
    const int warp = tid >> 5;
    const int lane = tid & 31;
    const int wm   = warp & 1;     // 2 warps along M (32 rows each)
    const int wn   = warp >> 1;    // 4 warps along N (64 cols each)
    const int bm   = blockIdx.x * EBM;
    const int g    = lane >> 2;
    const int tg   = lane & 3;

    const int arow = tid >> 2;         // 0..63
    const int ac   = (tid & 3) * 4;    // 0,4,8,12

    s_cs[tid] = 0.f;
    s_cq[tid] = 0.f;
    if (tid < EBM) { s_dotf[tid] = 0.f; s_dotb[tid] = 0.f; }

    float acc[2][8][4];
#pragma unroll
    for (int i = 0; i < 2; i++)
#pragma unroll
        for (int j = 0; j < 8; j++)
#pragma unroll
            for (int q = 0; q < 4; q++) acc[i][j][q] = 0.f;

    float4 av;
    float4 bv[4];

    auto gload = [&](int k0) {
        const size_t roff = (size_t)(bm + arow) * 256 + k0 + ac;
        if (fuse) {
            float4 base = *(const float4*)(ebase + roff);
            float4 t    = *(const float4*)(etmp + roff);
            float4 m    = *(const float4*)(meane + k0 + ac);
            float4 rs   = *(const float4*)(rstde + k0 + ac);
            float4 ga   = *(const float4*)(gam + k0 + ac);
            float4 be_  = *(const float4*)(bet + k0 + ac);
            float x;
            x = (t.x - m.x) * rs.x * ga.x + be_.x; base.x += x > 0.f ? x : 0.f;
            x = (t.y - m.y) * rs.y * ga.y + be_.y; base.y += x > 0.f ? x : 0.f;
            x = (t.z - m.z) * rs.z * ga.z + be_.z; base.z += x > 0.f ? x : 0.f;
            x = (t.w - m.w) * rs.w * ga.w + be_.w; base.w += x > 0.f ? x : 0.f;
            *(float4*)(eout + roff) = base;
            av = base;
        } else {
            av = *(const float4*)(ebase + roff);
        }
#pragma unroll
        for (int it = 0; it < 4; it++) {
            const int slot = tid + it * 256;
            bv[it] = *(const float4*)(W + (size_t)(k0 + (slot >> 6)) * 256 + (slot & 63) * 4);
        }
    };
    auto sstore = [&](int s) {
        float4 v = av;
        v.x = ftf32(v.x); v.y = ftf32(v.y); v.z = ftf32(v.z); v.w = ftf32(v.w);
        *(float4*)(&As[s][arow][ac]) = v;
#pragma unroll
        for (int it = 0; it < 4; it++) {
            const int slot = tid + it * 256;
            v = bv[it];
            v.x = ftf32(v.x); v.y = ftf32(v.y); v.z = ftf32(v.z); v.w = ftf32(v.w);
            *(float4*)(&Bs[s][slot >> 6][(slot & 63) * 4]) = v;
        }
    };

    gload(0);
    sstore(0);
    __syncthreads();

#pragma unroll 2
    for (int kt = 0; kt < 16; kt++) {
        const int cur = kt & 1;
        if (kt < 15) gload((kt + 1) * EBK);

#pragma unroll
        for (int ks = 0; ks < 2; ks++) {
            const int k = ks * 8;
            unsigned af_[2][4];
#pragma unroll
            for (int mt = 0; mt < 2; mt++) {
                const int rb = wm * 32 + mt * 16;
                af_[mt][0] = __float_as_uint(As[cur][rb + g][k + tg]);
                af_[mt][1] = __float_as_uint(As[cur][rb + g + 8][k + tg]);
                af_[mt][2] = __float_as_uint(As[cur][rb + g][k + tg + 4]);
                af_[mt][3] = __float_as_uint(As[cur][rb + g + 8][k + tg + 4]);
            }
            unsigned bf[8][2];
#pragma unroll
            for (int nt = 0; nt < 8; nt++) {
                const int n = wn * 64 + nt * 8 + g;
                bf[nt][0] = __float_as_uint(Bs[cur][k + tg][n]);
                bf[nt][1] = __float_as_uint(Bs[cur][k + tg + 4][n]);
            }
#pragma unroll
            for (int mt = 0; mt < 2; mt++)
#pragma unroll
                for (int nt = 0; nt < 8; nt++)
                    mma8(acc[mt][nt], af_[mt], bf[nt]);
        }

        if (kt < 15) sstore((kt + 1) & 1);
        __syncthreads();
    }

    // ---- fused epilogue: gathers + etmp store + logits + BN stats ----
    int lr_[4], ss_[4], dd_[4];
    float dotf[4] = {0.f, 0.f, 0.f, 0.f};
    float dotb[4] = {0.f, 0.f, 0.f, 0.f};
#pragma unroll
    for (int mt = 0; mt < 2; mt++)
#pragma unroll
        for (int rr = 0; rr < 2; rr++) {
            const int i = mt * 2 + rr;
            lr_[i] = wm * 32 + mt * 16 + rr * 8 + g;
            const int r = bm + lr_[i];
            ss_[i] = __ldg(&src[r]);
            dd_[i] = __ldg(&dst[r]);
        }

#pragma unroll
    for (int nt = 0; nt < 8; nt++) {
        const int col = wn * 64 + nt * 8 + tg * 2;
        const float a0 = __ldg(attf + col), a1 = __ldg(attf + col + 1);
        const float b0 = __ldg(attb + col), b1 = __ldg(attb + col + 1);
        float cs0 = 0.f, cq0 = 0.f, cs1 = 0.f, cq1 = 0.f;
#pragma unroll
        for (int mt = 0; mt < 2; mt++)
#pragma unroll
            for (int rr = 0; rr < 2; rr++) {
                const int i = mt * 2 + rr;
                const int r = bm + lr_[i];
                float2 o = make_float2(acc[mt][nt][rr * 2], acc[mt][nt][rr * 2 + 1]);
                float2 gs = *(const float2*)(G0 + (size_t)ss_[i] * 256 + col);
                float2 gd = *(const float2*)(G1 + (size_t)dd_[i] * 256 + col);
                o.x += gs.x + gd.x;
                o.y += gs.y + gd.y;
                *(float2*)(etmp + (size_t)r * 256 + col) = o;
                cs0 += o.x; cq0 += o.x * o.x;
                cs1 += o.y; cq1 += o.y * o.y;
                dotf[i] = fmaf(o.x, a0, fmaf(o.y, a1, dotf[i]));
                dotb[i] = fmaf(o.x, b0, fmaf(o.y, b1, dotb[i]));
            }
        atomicAdd(&s_cs[col], cs0);
        atomicAdd(&s_cs[col + 1], cs1);
        atomicAdd(&s_cq[col], cq0);
        atomicAdd(&s_cq[col + 1], cq1);
    }
#pragma unroll
    for (int i = 0; i < 4; i++) {
        atomicAdd(&s_dotf[lr_[i]], dotf[i]);
        atomicAdd(&s_dotb[lr_[i]], dotb[i]);
    }
    __syncthreads();

    if (tid < EBM) {
        const float df = s_dotf[tid], db = s_dotb[tid];
        logf[bm + tid] = df > 0.f ? df : 0.2f * df;
        logb[bm + tid] = db > 0.f ? db : 0.2f * db;
    }
    atomicAdd(&sume[tid], s_cs[tid]);
    atomicAdd(&ssqe[tid], s_cq[tid]);
}

// ---------------- CSR build --------------------------------------------------
__global__ void k_zero_deg(int* __restrict__ df, int* __restrict__ db) {
    int i = blockIdx.x * blockDim.x + threadIdx.x;
    if (i < NNODE) { df[i] = 0; db[i] = 0; }
}
__global__ void k_count(const int* __restrict__ src, const int* __restrict__ dst,
                        int* __restrict__ degf, int* __restrict__ degb) {
    int e = blockIdx.x * blockDim.x + threadIdx.x;
    if (e >= NEDGE) return;
    atomicAdd(&degf[dst[e]], 1);
    atomicAdd(&degb[src[e]], 1);
}
__device__ void scan_one(const int* __restrict__ deg, int* __restrict__ rp,
                         int* __restrict__ cur, int* sm) {
    const int t  = threadIdx.x;
    const int CH = (NNODE + 1023) / 1024;
    int lo = t * CH;
    int hi = lo + CH; if (hi > NNODE) hi = NNODE;
    int s = 0;
    for (int i = lo; i < hi; i++) s += deg[i];
    sm[t] = s;
    __syncthreads();
    for (int off = 1; off < 1024; off <<= 1) {
        int v = (t >= off) ? sm[t - off] : 0;
        __syncthreads();
        sm[t] += v;
        __syncthreads();
    }
    int run = (t == 0) ? 0 : sm[t - 1];
    for (int i = lo; i < hi; i++) { rp[i] = run; cur[i] = run; run += deg[i]; }
    if (t == 1023) rp[NNODE] = run;
    __syncthreads();
}
__global__ void k_scan(const int* degf, const int* degb,
                       int* rpf, int* rpb, int* curf, int* curb) {
    __shared__ int sm[1024];
    scan_one(degf, rpf, curf, sm);
    scan_one(degb, rpb, curb, sm);
}
__global__ void k_fill(const int* __restrict__ src, const int* __restrict__ dst,
                       int* __restrict__ curf, int* __restrict__ curb,
                       int* __restrict__ eidf, int* __restrict__ eidb) {
    int e = blockIdx.x * blockDim.x + threadIdx.x;
    if (e >= NEDGE) return;
    int p = atomicAdd(&curf[dst[e]], 1);
    eidf[p] = e;
    int q = atomicAdd(&curb[src[e]], 1);
    eidb[q] = e;
}

// ---------------- BN stats ----------------------------------------------------
__global__ void k_zero_stats(float* __restrict__ sum, float* __restrict__ ssq) {
    int c = threadIdx.x;
    sum[c] = 0.f;
    ssq[c] = 0.f;
}
__global__ void k_colstats(const float* __restrict__ X, int M,
                           float* __restrict__ sum, float* __restrict__ ssq) {
    int c = threadIdx.x;
    long chunk = ((long)M + gridDim.x - 1) / gridDim.x;
    long r0 = (long)blockIdx.x * chunk;
    long r1 = r0 + chunk;
    if (r1 > M) r1 = M;
    float s = 0.f, q = 0.f;
    for (long r = r0; r < r1; r++) {
        float v = X[r * FDIM + c];
        s += v; q += v * v;
    }
    atomicAdd(&sum[c], s);
    atomicAdd(&ssq[c], q);
}
__global__ void k_bnfin(const float* __restrict__ sum, const float* __restrict__ ssq,
                        int M, float* __restrict__ mean, float* __restrict__ rstd) {
    int c = threadIdx.x;
    float mu  = sum[c] / (float)M;
    float var = ssq[c] / (float)M - mu * mu;
    mean[c] = mu;
    rstd[c] = rsqrtf(var + 1e-5f);
}

// ---------------- residual + BN + relu ---------------------------------------
__global__ void k_bnres(float4* __restrict__ out, const float4* __restrict__ in,
                        const float4* __restrict__ tmp,
                        const float4* __restrict__ mean, const float4* __restrict__ rstd,
                        const float4* __restrict__ gam, const float4* __restrict__ bet,
                        long n4) {
    long i = (long)blockIdx.x * blockDim.x + threadIdx.x;
    if (i >= n4) return;
    int c = (int)(i & 63);
    float4 t = tmp[i], v = in[i];
    float4 m = mean[c], r = rstd[c], g = gam[c], b = bet[c];
    float x;
    x = (t.x - m.x) * r.x * g.x + b.x; v.x += x > 0.f ? x : 0.f;
    x = (t.y - m.y) * r.y * g.y + b.y; v.y += x > 0.f ? x : 0.f;
    x = (t.z - m.z) * r.z * g.z + b.z; v.z += x > 0.f ? x : 0.f;
    x = (t.w - m.w) * r.w * g.w + b.w; v.w += x > 0.f ? x : 0.f;
    out[i] = v;
}

// ---------------- per-node softmax + aggregation (CSR gather, no atomics) ----
__device__ __forceinline__ float bred(float v, float* s, bool ismax) {
    const int lane = threadIdx.x & 31, warp = threadIdx.x >> 5;
#pragma unroll
    for (int o = 16; o > 0; o >>= 1) {
        float t = __shfl_xor_sync(0xffffffffu, v, o);
        v = ismax ? fmaxf(v, t) : v + t;
    }
    if (lane == 0) s[warp] = v;
    __syncthreads();
    if (threadIdx.x == 0) {
        float r = s[0];
#pragma unroll
        for (int i = 1; i < 8; i++) r = ismax ? fmaxf(r, s[i]) : r + s[i];
        s[0] = r;
    }
    __syncthreads();
    float r = s[0];
    __syncthreads();
    return r;
}

#define DEG_CAP 1024

__device__ float agg_one(int n, const int* __restrict__ rp, const int* __restrict__ eid,
                         const int* __restrict__ oth, const float* __restrict__ lg,
                         const float* __restrict__ feat,
                         int* s_i, float* s_a, float* s_red) {
    const int tid = threadIdx.x;
    const int beg = rp[n], end = rp[n + 1];
    const int deg = end - beg;
    if (deg == 0) return 0.f;
    const bool c = (deg <= DEG_CAP);

    float m = -3.4e38f;
    for (int j = tid; j < deg; j += 256) {
        int e = __ldg(&eid[beg + j]);
        float l = __ldg(&lg[e]);
        if (c) { s_i[j] = e; s_a[j] = l; }
        m = fmaxf(m, l);
    }
    m = bred(m, s_red, true);

    float den = 0.f;
    for (int j = tid; j < deg; j += 256) {
        int e = c ? s_i[j] : __ldg(&eid[beg + j]);
        float l = c ? s_a[j] : __ldg(&lg[e]);
        float ex = __expf(l - m);
        int o = __ldg(&oth[e]);
        if (c) { s_a[j] = ex; s_i[j] = o; }
        den += ex;
    }
    den = bred(den, s_red, false);
    const float rden = 1.f / (den + 1e-9f);

    float a0 = 0.f, a1 = 0.f, a2 = 0.f, a3 = 0.f;
    if (c) {
        int j = 0;
        for (; j + 4 <= deg; j += 4) {
            a0 = fmaf(s_a[j + 0], feat[(size_t)s_i[j + 0] * 256 + tid], a0);
            a1 = fmaf(s_a[j + 1], feat[(size_t)s_i[j + 1] * 256 + tid], a1);
            a2 = fmaf(s_a[j + 2], feat[(size_t)s_i[j + 2] * 256 + tid], a2);
            a3 = fmaf(s_a[j + 3], feat[(size_t)s_i[j + 3] * 256 + tid], a3);
        }
        for (; j < deg; j++)
            a0 = fmaf(s_a[j], feat[(size_t)s_i[j] * 256 + tid], a0);
    } else {
        for (int j = 0; j < deg; j++) {
            int e = __ldg(&eid[beg + j]);
            float ex = __expf(__ldg(&lg[e]) - m);
            int o = __ldg(&oth[e]);
            a0 = fmaf(ex, feat[(size_t)o * 256 + tid], a0);
        }
    }
    return ((a0 + a1) + (a2 + a3)) * rden;
}

__global__ __launch_bounds__(256)
void k_node_agg(const int* __restrict__ rpf, const int* __restrict__ eidf,
                const int* __restrict__ src,
                const int* __restrict__ rpb, const int* __restrict__ eidb,
                const int* __restrict__ dst,
                const float* __restrict__ lf, const float* __restrict__ lb,
                const float* __restrict__ hwf, const float* __restrict__ hwb,
                float* __restrict__ htmp) {
    __shared__ int   s_i[DEG_CAP];
    __shared__ float s_a[DEG_CAP];
    __shared__ float s_red[8];
    const int n = blockIdx.x;
    float acc = agg_one(n, rpf, eidf, src, lf, hwf, s_i, s_a, s_red);
    __syncthreads();
    acc += agg_one(n, rpb, eidb, dst, lb, hwb, s_i, s_a, s_red);
    htmp[(size_t)n * 256 + threadIdx.x] += acc;
}

// ---------------- launcher ---------------------------------------------------
extern "C" void kernel_launch(void* const* d_in, const int* in_sizes, int n_in,
                              void* d_out, int out_size) {
    const float* in_h   = (const float*)d_in[0];
    const float* in_e   = (const float*)d_in[1];
    const int*   src    = (const int*)d_in[2];
    const int*   dst    = (const int*)d_in[3];
    const float* We     = (const float*)d_in[4];
    const float* Ws     = (const float*)d_in[5];
    const float* Wd     = (const float*)d_in[6];
    const float* Wself  = (const float*)d_in[7];
    const float* Wf     = (const float*)d_in[8];
    const float* Wb     = (const float*)d_in[9];
    const float* att_f  = (const float*)d_in[10];
    const float* att_b  = (const float*)d_in[11];
    const float* ge     = (const float*)d_in[12];
    const float* be     = (const float*)d_in[13];
    const float* gh     = (const float*)d_in[14];
    const float* bh     = (const float*)d_in[15];

    float* h_out = (float*)d_out;
    float* e_out = (float*)d_out + (size_t)NNODE * FDIM;

    float *etmp, *hw, *logf, *logb;
    float *sum, *ssq, *mean, *rstd, *sume, *ssqe, *meane, *rstde;
    int *degf, *degb, *rpf, *rpb, *curf, *curb, *eidf, *eidb;
    cudaGetSymbolAddress((void**)&etmp,  g_etmp);
    cudaGetSymbolAddress((void**)&hw,    g_hw);
    cudaGetSymbolAddress((void**)&logf,  g_logf);
    cudaGetSymbolAddress((void**)&logb,  g_logb);
    cudaGetSymbolAddress((void**)&degf,  g_degf);
    cudaGetSymbolAddress((void**)&degb,  g_degb);
    cudaGetSymbolAddress((void**)&rpf,   g_rpf);
    cudaGetSymbolAddress((void**)&rpb,   g_rpb);
    cudaGetSymbolAddress((void**)&curf,  g_curf);
    cudaGetSymbolAddress((void**)&curb,  g_curb);
    cudaGetSymbolAddress((void**)&eidf,  g_eidf);
    cudaGetSymbolAddress((void**)&eidb,  g_eidb);
    cudaGetSymbolAddress((void**)&sum,   g_sum);
    cudaGetSymbolAddress((void**)&ssq,   g_ssq);
    cudaGetSymbolAddress((void**)&mean,  g_mean);
    cudaGetSymbolAddress((void**)&rstd,  g_rstd);
    cudaGetSymbolAddress((void**)&sume,  g_sume);
    cudaGetSymbolAddress((void**)&ssqe,  g_ssqe);
    cudaGetSymbolAddress((void**)&meane, g_meane);
    cudaGetSymbolAddress((void**)&rstde, g_rstde);

    const size_t NF = (size_t)NNODE * FDIM;
    float* hws  = hw + 0 * NF;
    float* hwd  = hw + 1 * NF;
    float* hwf  = hw + 2 * NF;
    float* hwb  = hw + 3 * NF;
    float* htmp = hw + 4 * NF;

    // ---- CSR build (graph static across layers) ----
    k_zero_deg<<<(NNODE + 255) / 256, 256>>>(degf, degb);
    k_count<<<(NEDGE + 255) / 256, 256>>>(src, dst, degf, degb);
    k_scan<<<1, 1024>>>(degf, degb, rpf, rpb, curf, curb);
    k_fill<<<(NEDGE + 255) / 256, 256>>>(src, dst, curf, curb, eidf, eidb);

    dim3 gN((NNODE + BM - 1) / BM, 2, 5);
    dim3 gE(NEDGE / EBM, 1);

    for (int l = 0; l < NL; l++) {
        const float* h_in = (l == 0) ? in_h : h_out;
        size_t WO = (size_t)l * FDIM * FDIM;
        size_t VO = (size_t)l * FDIM;

        NodeGemmParams p;
        p.W[0] = Ws + WO;    p.C[0] = hws;
        p.W[1] = Wd + WO;    p.C[1] = hwd;
        p.W[2] = Wf + WO;    p.C[2] = hwf;
        p.W[3] = Wb + WO;    p.C[3] = hwb;
        p.W[4] = Wself + WO; p.C[4] = htmp;
        tgemm_node<<<gN, 256>>>(h_in, p, NNODE);

        // edge GEMM with fused prev-layer bnres (prologue) and
        // fused logits + BN-stats (epilogue)
        k_zero_stats<<<1, 256>>>(sume, ssqe);
        const float* ebase = (l == 0) ? in_e : ((l == 1) ? in_e : e_out);
        tgemm_edge_f<<<gE, 256>>>(ebase, etmp, e_out, We + WO,
                                  hws, hwd, src, dst,
                                  meane, rstde, ge + ((size_t)(l - 1) * FDIM),
                                  be + ((size_t)(l - 1) * FDIM),
                                  att_f + VO, att_b + VO,
                                  logf, logb, sume, ssqe, (l > 0) ? 1 : 0);
        k_bnfin<<<1, 256>>>(sume, ssqe, NEDGE, meane, rstde);

        // final layer: materialize e_out = e_new_3 (no next GEMM to fuse into)
        if (l == NL - 1) {
            k_bnres<<<(int)(((long)NEDGE * 64 + 255) / 256), 256>>>(
                (float4*)e_out, (const float4*)e_out, (const float4*)etmp,
                (const float4*)meane, (const float4*)rstde,
                (const float4*)(ge + VO), (const float4*)(be + VO), (long)NEDGE * 64);
        }

        // per-node softmax + aggregation (both directions), no atomics
        k_node_agg<<<NNODE, 256>>>(rpf, eidf, src, rpb, eidb, dst,
                                   logf, logb, hwf, hwb, htmp);

        // node BN + residual
        k_zero_stats<<<1, 256>>>(sum, ssq);
        k_colstats<<<256, 256>>>(htmp, NNODE, sum, ssq);
        k_bnfin<<<1, 256>>>(sum, ssq, NNODE, mean, rstd);
        k_bnres<<<(int)(((long)NNODE * 64 + 255) / 256), 256>>>(
            (float4*)h_out, (const float4*)h_in, (const float4*)htmp,
            (const float4*)mean, (const float4*)rstd,
            (const float4*)(gh + VO), (const float4*)(bh + VO), (long)NNODE * 64);
    }
}

// round 9
// speedup vs baseline: 1.8932x; 1.8932x over previous
#include <cuda_runtime.h>
#include <cuda_fp16.h>

#define NL 4
#define NNODE 50000
#define NEDGE 800000
#define FDIM 256

// ---------------- scratch (static device globals; no allocation allowed) ----
__device__ float    g_etmp[(size_t)NEDGE * FDIM];       // e_tmp  [E,F]
__device__ float    g_hw[(size_t)5 * NNODE * FDIM];     // hWs,hWd,hWf,hWb,h_tmp
__device__ float    g_logf[NEDGE];
__device__ float    g_logb[NEDGE];
__device__ int      g_degf[NNODE], g_degb[NNODE];
__device__ int      g_rpf[NNODE + 1], g_rpb[NNODE + 1];
__device__ int      g_curf[NNODE], g_curb[NNODE];
__device__ int      g_eidf[NEDGE], g_eidb[NEDGE];
__device__ float    g_sum[FDIM], g_ssq[FDIM], g_mean[FDIM], g_rstd[FDIM];

// ---------------- helpers ----------------------------------------------------
__device__ __forceinline__ void mma16(float* c, const unsigned* a, const unsigned* b) {
    asm volatile(
        "mma.sync.aligned.m16n8k16.row.col.f32.f16.f16.f32 "
        "{%0,%1,%2,%3}, {%4,%5,%6,%7}, {%8,%9}, {%0,%1,%2,%3};"
        : "+f"(c[0]), "+f"(c[1]), "+f"(c[2]), "+f"(c[3])
        : "r"(a[0]), "r"(a[1]), "r"(a[2]), "r"(a[3]), "r"(b[0]), "r"(b[1]));
}
__device__ __forceinline__ void ldsm4(unsigned& r0, unsigned& r1, unsigned& r2, unsigned& r3,
                                      unsigned a) {
    asm volatile("ldmatrix.sync.aligned.m8n8.x4.shared.b16 {%0,%1,%2,%3}, [%4];"
                 : "=r"(r0), "=r"(r1), "=r"(r2), "=r"(r3) : "r"(a));
}
__device__ __forceinline__ void ldsm4t(unsigned& r0, unsigned& r1, unsigned& r2, unsigned& r3,
                                       unsigned a) {
    asm volatile("ldmatrix.sync.aligned.m8n8.x4.trans.shared.b16 {%0,%1,%2,%3}, [%4];"
                 : "=r"(r0), "=r"(r1), "=r"(r2), "=r"(r3) : "r"(a));
}
__device__ __forceinline__ uint4 pack8h(float4 a, float4 b) {
    __half2 h0 = __floats2half2_rn(a.x, a.y);
    __half2 h1 = __floats2half2_rn(a.z, a.w);
    __half2 h2 = __floats2half2_rn(b.x, b.y);
    __half2 h3 = __floats2half2_rn(b.z, b.w);
    uint4 u;
    u.x = *(unsigned*)&h0; u.y = *(unsigned*)&h1;
    u.z = *(unsigned*)&h2; u.w = *(unsigned*)&h3;
    return u;
}

// ---------------- FP16 tensor-core GEMM body ---------------------------------
// C[M,256] = A[M,256] @ W[256,256] (+ optional edge gathers in epilogue)
// Block tile 128x128 (grid.y selects 128-col panel), BK=16, 256 threads,
// 8 warps (4 along M x 2 along N), warp tile 32x64. fp16 inputs, fp32 accum.
#define BM 128
#define BK 16
#define APADH 24    // As row stride in halfs (48B) -> conflict-free ldmatrix
#define BPADH 136   // Bs row stride in halfs (272B) -> conflict-free ldmatrix

template <bool EDGE>
__device__ __forceinline__ void gemm_body(
    const float* __restrict__ A, const float* __restrict__ W,
    float* __restrict__ C, int M,
    const float* __restrict__ G0, const float* __restrict__ G1,
    const int* __restrict__ src, const int* __restrict__ dst)
{
    __shared__ __align__(16) __half As[2][BM][APADH];
    __shared__ __align__(16) __half Bs[2][BK][BPADH];

    const int tid  = threadIdx.x;
    const int warp = tid >> 5;
    const int lane = tid & 31;
    const int wm   = warp & 3;     // m offset = wm*32
    const int wn   = warp >> 2;    // n offset = wn*64
    const int bm   = blockIdx.x * BM;
    const int bn   = blockIdx.y * 128;
    const int g    = lane >> 2;
    const int tg   = lane & 3;

    // global load mapping
    const int ar = tid >> 1;          // A row 0..127
    const int ak = (tid & 1) * 8;     // A k-half 0/8
    const int bk = tid >> 4;          // B k-row 0..15
    const int bq = (tid & 15) * 8;    // B n-offset 0..120

    float acc[2][8][4];
#pragma unroll
    for (int i = 0; i < 2; i++)
#pragma unroll
        for (int j = 0; j < 8; j++)
#pragma unroll
            for (int q = 0; q < 4; q++) acc[i][j][q] = 0.f;

    float4 a0v, a1v, b0v, b1v;

    auto gload = [&](int k0) {
        const float4 z = make_float4(0.f, 0.f, 0.f, 0.f);
        const int row = bm + ar;
        if (row < M) {
            a0v = *(const float4*)(A + (size_t)row * 256 + k0 + ak);
            a1v = *(const float4*)(A + (size_t)row * 256 + k0 + ak + 4);
        } else { a0v = z; a1v = z; }
        b0v = *(const float4*)(W + (size_t)(k0 + bk) * 256 + bn + bq);
        b1v = *(const float4*)(W + (size_t)(k0 + bk) * 256 + bn + bq + 4);
    };
    auto sstore = [&](int s) {
        *(uint4*)(&As[s][ar][ak]) = pack8h(a0v, a1v);
        *(uint4*)(&Bs[s][bk][bq]) = pack8h(b0v, b1v);
    };

    gload(0);
    sstore(0);
    __syncthreads();

#pragma unroll 2
    for (int kt = 0; kt < 16; kt++) {
        const int cur = kt & 1;
        if (kt < 15) gload((kt + 1) * BK);

        // fragment loads via ldmatrix
        unsigned af[2][4];
#pragma unroll
        for (int mt = 0; mt < 2; mt++) {
            unsigned sa = (unsigned)__cvta_generic_to_shared(
                &As[cur][wm * 32 + mt * 16 + (lane & 15)][(lane >> 4) * 8]);
            ldsm4(af[mt][0], af[mt][1], af[mt][2], af[mt][3], sa);
        }
        unsigned bf[8][2];
#pragma unroll
        for (int j = 0; j < 4; j++) {
            unsigned sb = (unsigned)__cvta_generic_to_shared(
                &Bs[cur][lane & 15][wn * 64 + j * 16 + (lane >> 4) * 8]);
            unsigned t0, t1, t2, t3;
            ldsm4t(t0, t1, t2, t3, sb);
            bf[2 * j][0] = t0; bf[2 * j][1] = t1;
            bf[2 * j + 1][0] = t2; bf[2 * j + 1][1] = t3;
        }
#pragma unroll
        for (int mt = 0; mt < 2; mt++)
#pragma unroll
            for (int nt = 0; nt < 8; nt++)
                mma16(acc[mt][nt], af[mt], bf[nt]);

        if (kt < 15) sstore((kt + 1) & 1);
        __syncthreads();
    }

#pragma unroll
    for (int mt = 0; mt < 2; mt++) {
#pragma unroll
        for (int rr = 0; rr < 2; rr++) {
            const int r = bm + wm * 32 + mt * 16 + rr * 8 + g;
            if (r < M) {
                int s = 0, d = 0;
                if (EDGE) { s = src[r]; d = dst[r]; }
#pragma unroll
                for (int nt = 0; nt < 8; nt++) {
                    const int col = bn + wn * 64 + nt * 8 + tg * 2;
                    float2 o = make_float2(acc[mt][nt][rr * 2], acc[mt][nt][rr * 2 + 1]);
                    if (EDGE) {
                        float2 gs = *(const float2*)(G0 + (size_t)s * 256 + col);
                        float2 gd = *(const float2*)(G1 + (size_t)d * 256 + col);
                        o.x += gs.x + gd.x;
                        o.y += gs.y + gd.y;
                    }
                    *(float2*)(C + (size_t)r * 256 + col) = o;
                }
            }
        }
    }
}

// batched node GEMM: blockIdx.z selects which of 5 weight/output pairs
struct NodeGemmParams { const float* W[5]; float* C[5]; };

__global__ __launch_bounds__(256)
void tgemm_node(const float* __restrict__ A, NodeGemmParams p, int M) {
    gemm_body<false>(A, p.W[blockIdx.z], p.C[blockIdx.z], M,
                     nullptr, nullptr, nullptr, nullptr);
}

__global__ __launch_bounds__(256)
void tgemm_edge(const float* __restrict__ A, const float* __restrict__ W,
                float* __restrict__ C, int M,
                const float* __restrict__ G0, const float* __restrict__ G1,
                const int* __restrict__ src, const int* __restrict__ dst) {
    gemm_body<true>(A, W, C, M, G0, G1, src, dst);
}

// ---------------- CSR build --------------------------------------------------
__global__ void k_zero_deg(int* __restrict__ df, int* __restrict__ db) {
    int i = blockIdx.x * blockDim.x + threadIdx.x;
    if (i < NNODE) { df[i] = 0; db[i] = 0; }
}
__global__ void k_count(const int* __restrict__ src, const int* __restrict__ dst,
                        int* __restrict__ degf, int* __restrict__ degb) {
    int e = blockIdx.x * blockDim.x + threadIdx.x;
    if (e >= NEDGE) return;
    atomicAdd(&degf[dst[e]], 1);
    atomicAdd(&degb[src[e]], 1);
}
__device__ void scan_one(const int* __restrict__ deg, int* __restrict__ rp,
                         int* __restrict__ cur, int* sm) {
    const int t  = threadIdx.x;
    const int CH = (NNODE + 1023) / 1024;
    int lo = t * CH;
    int hi = lo + CH; if (hi > NNODE) hi = NNODE;
    int s = 0;
    for (int i = lo; i < hi; i++) s += deg[i];
    sm[t] = s;
    __syncthreads();
    for (int off = 1; off < 1024; off <<= 1) {
        int v = (t >= off) ? sm[t - off] : 0;
        __syncthreads();
        sm[t] += v;
        __syncthreads();
    }
    int run = (t == 0) ? 0 : sm[t - 1];
    for (int i = lo; i < hi; i++) { rp[i] = run; cur[i] = run; run += deg[i]; }
    if (t == 1023) rp[NNODE] = run;
    __syncthreads();
}
__global__ void k_scan(const int* degf, const int* degb,
                       int* rpf, int* rpb, int* curf, int* curb) {
    __shared__ int sm[1024];
    scan_one(degf, rpf, curf, sm);
    scan_one(degb, rpb, curb, sm);
}
__global__ void k_fill(const int* __restrict__ src, const int* __restrict__ dst,
                       int* __restrict__ curf, int* __restrict__ curb,
                       int* __restrict__ eidf, int* __restrict__ eidb) {
    int e = blockIdx.x * blockDim.x + threadIdx.x;
    if (e >= NEDGE) return;
    int p = atomicAdd(&curf[dst[e]], 1);
    eidf[p] = e;
    int q = atomicAdd(&curb[src[e]], 1);
    eidb[q] = e;
}

// ---------------- fused edge colstats + attention logits ---------------------
__global__ __launch_bounds__(256)
void k_estats(const float* __restrict__ X,
              const float* __restrict__ af, const float* __restrict__ ab,
              float* __restrict__ lf, float* __restrict__ lb,
              float* __restrict__ sum, float* __restrict__ ssq) {
    __shared__ float s_s[256], s_q[256];
    const int tid = threadIdx.x, lane = tid & 31, warp = tid >> 5;
    s_s[tid] = 0.f; s_q[tid] = 0.f;
    __syncthreads();

    const float4* af4 = (const float4*)af;
    const float4* ab4 = (const float4*)ab;
    const float4 fa0 = af4[lane], fa1 = af4[lane + 32];
    const float4 ba0 = ab4[lane], ba1 = ab4[lane + 32];

    float cs[8] = {0}, cq[8] = {0};

    long w  = (long)blockIdx.x * 8 + warp;
    long nw = (long)gridDim.x * 8;
    for (long r = w; r < NEDGE; r += nw) {
        const float4* row = (const float4*)(X + r * 256);
        float4 v0 = row[lane], v1 = row[lane + 32];
        cs[0] += v0.x; cs[1] += v0.y; cs[2] += v0.z; cs[3] += v0.w;
        cs[4] += v1.x; cs[5] += v1.y; cs[6] += v1.z; cs[7] += v1.w;
        cq[0] += v0.x * v0.x; cq[1] += v0.y * v0.y; cq[2] += v0.z * v0.z; cq[3] += v0.w * v0.w;
        cq[4] += v1.x * v1.x; cq[5] += v1.y * v1.y; cq[6] += v1.z * v1.z; cq[7] += v1.w * v1.w;
        float df = v0.x * fa0.x + v0.y * fa0.y + v0.z * fa0.z + v0.w * fa0.w
                 + v1.x * fa1.x + v1.y * fa1.y + v1.z * fa1.z + v1.w * fa1.w;
        float db = v0.x * ba0.x + v0.y * ba0.y + v0.z * ba0.z + v0.w * ba0.w
                 + v1.x * ba1.x + v1.y * ba1.y + v1.z * ba1.z + v1.w * ba1.w;
#pragma unroll
        for (int o = 16; o > 0; o >>= 1) {
            df += __shfl_xor_sync(0xffffffffu, df, o);
            db += __shfl_xor_sync(0xffffffffu, db, o);
        }
        if (lane == 0) {
            lf[r] = df > 0.f ? df : 0.2f * df;
            lb[r] = db > 0.f ? db : 0.2f * db;
        }
    }
#pragma unroll
    for (int k = 0; k < 4; k++) {
        atomicAdd(&s_s[lane * 4 + k], cs[k]);
        atomicAdd(&s_s[128 + lane * 4 + k], cs[4 + k]);
        atomicAdd(&s_q[lane * 4 + k], cq[k]);
        atomicAdd(&s_q[128 + lane * 4 + k], cq[4 + k]);
    }
    __syncthreads();
    atomicAdd(&sum[tid], s_s[tid]);
    atomicAdd(&ssq[tid], s_q[tid]);
}

// ---------------- BN stats (node-side) ---------------------------------------
__global__ void k_zero_stats(float* __restrict__ sum, float* __restrict__ ssq) {
    int c = threadIdx.x;
    sum[c] = 0.f;
    ssq[c] = 0.f;
}
__global__ void k_colstats(const float* __restrict__ X, int M,
                           float* __restrict__ sum, float* __restrict__ ssq) {
    int c = threadIdx.x;
    long chunk = ((long)M + gridDim.x - 1) / gridDim.x;
    long r0 = (long)blockIdx.x * chunk;
    long r1 = r0 + chunk;
    if (r1 > M) r1 = M;
    float s = 0.f, q = 0.f;
    for (long r = r0; r < r1; r++) {
        float v = X[r * FDIM + c];
        s += v; q += v * v;
    }
    atomicAdd(&sum[c], s);
    atomicAdd(&ssq[c], q);
}
__global__ void k_bnfin(const float* __restrict__ sum, const float* __restrict__ ssq,
                        int M, float* __restrict__ mean, float* __restrict__ rstd) {
    int c = threadIdx.x;
    float mu  = sum[c] / (float)M;
    float var = ssq[c] / (float)M - mu * mu;
    mean[c] = mu;
    rstd[c] = rsqrtf(var + 1e-5f);
}

// ---------------- residual + BN + relu ---------------------------------------
__global__ void k_bnres(float4* __restrict__ out, const float4* __restrict__ in,
                        const float4* __restrict__ tmp,
                        const float4* __restrict__ mean, const float4* __restrict__ rstd,
                        const float4* __restrict__ gam, const float4* __restrict__ bet,
                        long n4) {
    long i = (long)blockIdx.x * blockDim.x + threadIdx.x;
    if (i >= n4) return;
    int c = (int)(i & 63);
    float4 t = tmp[i], v = in[i];
    float4 m = mean[c], r = rstd[c], g = gam[c], b = bet[c];
    float x;
    x = (t.x - m.x) * r.x * g.x + b.x; v.x += x > 0.f ? x : 0.f;
    x = (t.y - m.y) * r.y * g.y + b.y; v.y += x > 0.f ? x : 0.f;
    x = (t.z - m.z) * r.z * g.z + b.z; v.z += x > 0.f ? x : 0.f;
    x = (t.w - m.w) * r.w * g.w + b.w; v.w += x > 0.f ? x : 0.f;
    out[i] = v;
}

// ---------------- per-node softmax + aggregation (CSR gather, no atomics) ----
__device__ __forceinline__ float bred(float v, float* s, bool ismax) {
    const int lane = threadIdx.x & 31, warp = threadIdx.x >> 5;
#pragma unroll
    for (int o = 16; o > 0; o >>= 1) {
        float t = __shfl_xor_sync(0xffffffffu, v, o);
        v = ismax ? fmaxf(v, t) : v + t;
    }
    if (lane == 0) s[warp] = v;
    __syncthreads();
    if (threadIdx.x == 0) {
        float r = s[0];
#pragma unroll
        for (int i = 1; i < 8; i++) r = ismax ? fmaxf(r, s[i]) : r + s[i];
        s[0] = r;
    }
    __syncthreads();
    float r = s[0];
    __syncthreads();
    return r;
}

#define DEG_CAP 1024

__device__ float agg_one(int n, const int* __restrict__ rp, const int* __restrict__ eid,
                         const int* __restrict__ oth, const float* __restrict__ lg,
                         const float* __restrict__ feat,
                         int* s_i, float* s_a, float* s_red) {
    const int tid = threadIdx.x;
    const int beg = rp[n], end = rp[n + 1];
    const int deg = end - beg;
    if (deg == 0) return 0.f;
    const bool c = (deg <= DEG_CAP);

    float m = -3.4e38f;
    for (int j = tid; j < deg; j += 256) {
        int e = __ldg(&eid[beg + j]);
        float l = __ldg(&lg[e]);
        if (c) { s_i[j] = e; s_a[j] = l; }
        m = fmaxf(m, l);
    }
    m = bred(m, s_red, true);

    float den = 0.f;
    for (int j = tid; j < deg; j += 256) {
        int e = c ? s_i[j] : __ldg(&eid[beg + j]);
        float l = c ? s_a[j] : __ldg(&lg[e]);
        float ex = __expf(l - m);
        int o = __ldg(&oth[e]);
        if (c) { s_a[j] = ex; s_i[j] = o; }
        den += ex;
    }
    den = bred(den, s_red, false);
    const float rden = 1.f / (den + 1e-9f);

    float a0 = 0.f, a1 = 0.f, a2 = 0.f, a3 = 0.f;
    if (c) {
        int j = 0;
        for (; j + 4 <= deg; j += 4) {
            a0 = fmaf(s_a[j + 0], feat[(size_t)s_i[j + 0] * 256 + tid], a0);
            a1 = fmaf(s_a[j + 1], feat[(size_t)s_i[j + 1] * 256 + tid], a1);
            a2 = fmaf(s_a[j + 2], feat[(size_t)s_i[j + 2] * 256 + tid], a2);
            a3 = fmaf(s_a[j + 3], feat[(size_t)s_i[j + 3] * 256 + tid], a3);
        }
        for (; j < deg; j++)
            a0 = fmaf(s_a[j], feat[(size_t)s_i[j] * 256 + tid], a0);
    } else {
        for (int j = 0; j < deg; j++) {
            int e = __ldg(&eid[beg + j]);
            float ex = __expf(__ldg(&lg[e]) - m);
            int o = __ldg(&oth[e]);
            a0 = fmaf(ex, feat[(size_t)o * 256 + tid], a0);
        }
    }
    return ((a0 + a1) + (a2 + a3)) * rden;
}

__global__ __launch_bounds__(256)
void k_node_agg(const int* __restrict__ rpf, const int* __restrict__ eidf,
                const int* __restrict__ src,
                const int* __restrict__ rpb, const int* __restrict__ eidb,
                const int* __restrict__ dst,
                const float* __restrict__ lf, const float* __restrict__ lb,
                const float* __restrict__ hwf, const float* __restrict__ hwb,
                float* __restrict__ htmp) {
    __shared__ int   s_i[DEG_CAP];
    __shared__ float s_a[DEG_CAP];
    __shared__ float s_red[8];
    const int n = blockIdx.x;
    float acc = agg_one(n, rpf, eidf, src, lf, hwf, s_i, s_a, s_red);
    __syncthreads();
    acc += agg_one(n, rpb, eidb, dst, lb, hwb, s_i, s_a, s_red);
    htmp[(size_t)n * 256 + threadIdx.x] += acc;
}

// ---------------- launcher ---------------------------------------------------
extern "C" void kernel_launch(void* const* d_in, const int* in_sizes, int n_in,
                              void* d_out, int out_size) {
    const float* in_h   = (const float*)d_in[0];
    const float* in_e   = (const float*)d_in[1];
    const int*   src    = (const int*)d_in[2];
    const int*   dst    = (const int*)d_in[3];
    const float* We     = (const float*)d_in[4];
    const float* Ws     = (const float*)d_in[5];
    const float* Wd     = (const float*)d_in[6];
    const float* Wself  = (const float*)d_in[7];
    const float* Wf     = (const float*)d_in[8];
    const float* Wb     = (const float*)d_in[9];
    const float* att_f  = (const float*)d_in[10];
    const float* att_b  = (const float*)d_in[11];
    const float* ge     = (const float*)d_in[12];
    const float* be     = (const float*)d_in[13];
    const float* gh     = (const float*)d_in[14];
    const float* bh     = (const float*)d_in[15];

    float* h_out = (float*)d_out;
    float* e_out = (float*)d_out + (size_t)NNODE * FDIM;

    float *etmp, *hw, *logf, *logb, *sum, *ssq, *mean, *rstd;
    int *degf, *degb, *rpf, *rpb, *curf, *curb, *eidf, *eidb;
    cudaGetSymbolAddress((void**)&etmp, g_etmp);
    cudaGetSymbolAddress((void**)&hw,   g_hw);
    cudaGetSymbolAddress((void**)&logf, g_logf);
    cudaGetSymbolAddress((void**)&logb, g_logb);
    cudaGetSymbolAddress((void**)&degf, g_degf);
    cudaGetSymbolAddress((void**)&degb, g_degb);
    cudaGetSymbolAddress((void**)&rpf,  g_rpf);
    cudaGetSymbolAddress((void**)&rpb,  g_rpb);
    cudaGetSymbolAddress((void**)&curf, g_curf);
    cudaGetSymbolAddress((void**)&curb, g_curb);
    cudaGetSymbolAddress((void**)&eidf, g_eidf);
    cudaGetSymbolAddress((void**)&eidb, g_eidb);
    cudaGetSymbolAddress((void**)&sum,  g_sum);
    cudaGetSymbolAddress((void**)&ssq,  g_ssq);
    cudaGetSymbolAddress((void**)&mean, g_mean);
    cudaGetSymbolAddress((void**)&rstd, g_rstd);

    const size_t NF = (size_t)NNODE * FDIM;
    float* hws  = hw + 0 * NF;
    float* hwd  = hw + 1 * NF;
    float* hwf  = hw + 2 * NF;
    float* hwb  = hw + 3 * NF;
    float* htmp = hw + 4 * NF;

    // ---- CSR build (once per launch; graph is static across layers) ----
    k_zero_deg<<<(NNODE + 255) / 256, 256>>>(degf, degb);
    k_count<<<(NEDGE + 255) / 256, 256>>>(src, dst, degf, degb);
    k_scan<<<1, 1024>>>(degf, degb, rpf, rpb, curf, curb);
    k_fill<<<(NEDGE + 255) / 256, 256>>>(src, dst, curf, curb, eidf, eidb);

    dim3 gN((NNODE + BM - 1) / BM, 2, 5);
    dim3 gE(NEDGE / BM, 2);

    for (int l = 0; l < NL; l++) {
        const float* h_in = (l == 0) ? in_h : h_out;
        const float* e_in = (l == 0) ? in_e : e_out;
        size_t WO = (size_t)l * FDIM * FDIM;
        size_t VO = (size_t)l * FDIM;

        NodeGemmParams p;
        p.W[0] = Ws + WO;    p.C[0] = hws;
        p.W[1] = Wd + WO;    p.C[1] = hwd;
        p.W[2] = Wf + WO;    p.C[2] = hwf;
        p.W[3] = Wb + WO;    p.C[3] = hwb;
        p.W[4] = Wself + WO; p.C[4] = htmp;
        tgemm_node<<<gN, 256>>>(h_in, p, NNODE);

        tgemm_edge<<<gE, 256>>>(e_in, We + WO, etmp, NEDGE, hws, hwd, src, dst);

        // fused edge BN stats + attention logits (one pass over etmp)
        k_zero_stats<<<1, 256>>>(sum, ssq);
        k_estats<<<1024, 256>>>(etmp, att_f + VO, att_b + VO, logf, logb, sum, ssq);
        k_bnfin<<<1, 256>>>(sum, ssq, NEDGE, mean, rstd);

        // e_new = e + relu(bn(e_tmp))
        k_bnres<<<(int)(((long)NEDGE * 64 + 255) / 256), 256>>>(
            (float4*)e_out, (const float4*)e_in, (const float4*)etmp,
            (const float4*)mean, (const float4*)rstd,
            (const float4*)(ge + VO), (const float4*)(be + VO), (long)NEDGE * 64);

        // per-node softmax + aggregation (both directions), no atomics
        k_node_agg<<<NNODE, 256>>>(rpf, eidf, src, rpb, eidb, dst,
                                   logf, logb, hwf, hwb, htmp);

        // node BN + residual
        k_zero_stats<<<1, 256>>>(sum, ssq);
        k_colstats<<<256, 256>>>(htmp, NNODE, sum, ssq);
        k_bnfin<<<1, 256>>>(sum, ssq, NNODE, mean, rstd);
        k_bnres<<<(int)(((long)NNODE * 64 + 255) / 256), 256>>>(
            (float4*)h_out, (const float4*)h_in, (const float4*)htmp,
            (const float4*)mean, (const float4*)rstd,
            (const float4*)(gh + VO), (const float4*)(bh + VO), (long)NNODE * 64);
    }
}

// round 10
// speedup vs baseline: 1.9897x; 1.0510x over previous
#include <cuda_runtime.h>
#include <cuda_fp16.h>

#define NL 4
#define NNODE 50000
#define NEDGE 800000
#define FDIM 256
#define NFC ((size_t)NNODE * FDIM)

// ---------------- scratch (static device globals; no allocation allowed) ----
__device__ float    g_etmp[(size_t)NEDGE * FDIM];       // e_tmp  [E,F]
__device__ __half   g_hwh[(size_t)4 * NNODE * FDIM];    // hWs,hWd,hWf,hWb (fp16)
__device__ float    g_htmp[(size_t)NNODE * FDIM];       // h@Wself + agg (fp32)
__device__ float    g_logf[NEDGE];
__device__ float    g_logb[NEDGE];
__device__ int      g_degf[NNODE], g_degb[NNODE];
__device__ int      g_rpf[NNODE + 1], g_rpb[NNODE + 1];
__device__ int      g_curf[NNODE], g_curb[NNODE];
__device__ int      g_eidf[NEDGE], g_eidb[NEDGE];
__device__ float    g_sum[FDIM], g_ssq[FDIM], g_mean[FDIM], g_rstd[FDIM];

// ---------------- helpers ----------------------------------------------------
__device__ __forceinline__ void mma16(float* c, const unsigned* a, const unsigned* b) {
    asm volatile(
        "mma.sync.aligned.m16n8k16.row.col.f32.f16.f16.f32 "
        "{%0,%1,%2,%3}, {%4,%5,%6,%7}, {%8,%9}, {%0,%1,%2,%3};"
        : "+f"(c[0]), "+f"(c[1]), "+f"(c[2]), "+f"(c[3])
        : "r"(a[0]), "r"(a[1]), "r"(a[2]), "r"(a[3]), "r"(b[0]), "r"(b[1]));
}
__device__ __forceinline__ void ldsm4(unsigned& r0, unsigned& r1, unsigned& r2, unsigned& r3,
                                      unsigned a) {
    asm volatile("ldmatrix.sync.aligned.m8n8.x4.shared.b16 {%0,%1,%2,%3}, [%4];"
                 : "=r"(r0), "=r"(r1), "=r"(r2), "=r"(r3) : "r"(a));
}
__device__ __forceinline__ void ldsm4t(unsigned& r0, unsigned& r1, unsigned& r2, unsigned& r3,
                                       unsigned a) {
    asm volatile("ldmatrix.sync.aligned.m8n8.x4.trans.shared.b16 {%0,%1,%2,%3}, [%4];"
                 : "=r"(r0), "=r"(r1), "=r"(r2), "=r"(r3) : "r"(a));
}
__device__ __forceinline__ uint4 pack8h(float4 a, float4 b) {
    __half2 h0 = __floats2half2_rn(a.x, a.y);
    __half2 h1 = __floats2half2_rn(a.z, a.w);
    __half2 h2 = __floats2half2_rn(b.x, b.y);
    __half2 h3 = __floats2half2_rn(b.z, b.w);
    uint4 u;
    u.x = *(unsigned*)&h0; u.y = *(unsigned*)&h1;
    u.z = *(unsigned*)&h2; u.w = *(unsigned*)&h3;
    return u;
}

// ---------------- FP16 tensor-core GEMM body ---------------------------------
// C[M,256] = A[M,256] @ W[256,256]
// EDGE: epilogue adds fp16-table gathers G0[src], G1[dst] and writes fp32.
// HALFOUT: epilogue writes fp16 (projection tables).
#define BM 128
#define BK 16
#define APADH 24
#define BPADH 136

template <bool EDGE, bool HALFOUT>
__device__ __forceinline__ void gemm_body(
    const float* __restrict__ A, const float* __restrict__ W,
    void* __restrict__ Cv, int M,
    const __half* __restrict__ G0, const __half* __restrict__ G1,
    const int* __restrict__ src, const int* __restrict__ dst)
{
    __shared__ __align__(16) __half As[2][BM][APADH];
    __shared__ __align__(16) __half Bs[2][BK][BPADH];

    const int tid  = threadIdx.x;
    const int warp = tid >> 5;
    const int lane = tid & 31;
    const int wm   = warp & 3;
    const int wn   = warp >> 2;
    const int bm   = blockIdx.x * BM;
    const int bn   = blockIdx.y * 128;
    const int g    = lane >> 2;
    const int tg   = lane & 3;

    const int ar = tid >> 1;
    const int ak = (tid & 1) * 8;
    const int bk = tid >> 4;
    const int bq = (tid & 15) * 8;

    float acc[2][8][4];
#pragma unroll
    for (int i = 0; i < 2; i++)
#pragma unroll
        for (int j = 0; j < 8; j++)
#pragma unroll
            for (int q = 0; q < 4; q++) acc[i][j][q] = 0.f;

    float4 a0v, a1v, b0v, b1v;

    auto gload = [&](int k0) {
        const float4 z = make_float4(0.f, 0.f, 0.f, 0.f);
        const int row = bm + ar;
        if (row < M) {
            a0v = *(const float4*)(A + (size_t)row * 256 + k0 + ak);
            a1v = *(const float4*)(A + (size_t)row * 256 + k0 + ak + 4);
        } else { a0v = z; a1v = z; }
        b0v = *(const float4*)(W + (size_t)(k0 + bk) * 256 + bn + bq);
        b1v = *(const float4*)(W + (size_t)(k0 + bk) * 256 + bn + bq + 4);
    };
    auto sstore = [&](int s) {
        *(uint4*)(&As[s][ar][ak]) = pack8h(a0v, a1v);
        *(uint4*)(&Bs[s][bk][bq]) = pack8h(b0v, b1v);
    };

    gload(0);
    sstore(0);
    __syncthreads();

#pragma unroll 2
    for (int kt = 0; kt < 16; kt++) {
        const int cur = kt & 1;
        if (kt < 15) gload((kt + 1) * BK);

        unsigned af[2][4];
#pragma unroll
        for (int mt = 0; mt < 2; mt++) {
            unsigned sa = (unsigned)__cvta_generic_to_shared(
                &As[cur][wm * 32 + mt * 16 + (lane & 15)][(lane >> 4) * 8]);
            ldsm4(af[mt][0], af[mt][1], af[mt][2], af[mt][3], sa);
        }
        unsigned bf[8][2];
#pragma unroll
        for (int j = 0; j < 4; j++) {
            unsigned sb = (unsigned)__cvta_generic_to_shared(
                &Bs[cur][lane & 15][wn * 64 + j * 16 + (lane >> 4) * 8]);
            unsigned t0, t1, t2, t3;
            ldsm4t(t0, t1, t2, t3, sb);
            bf[2 * j][0] = t0; bf[2 * j][1] = t1;
            bf[2 * j + 1][0] = t2; bf[2 * j + 1][1] = t3;
        }
#pragma unroll
        for (int mt = 0; mt < 2; mt++)
#pragma unroll
            for (int nt = 0; nt < 8; nt++)
                mma16(acc[mt][nt], af[mt], bf[nt]);

        if (kt < 15) sstore((kt + 1) & 1);
        __syncthreads();
    }

#pragma unroll
    for (int mt = 0; mt < 2; mt++) {
#pragma unroll
        for (int rr = 0; rr < 2; rr++) {
            const int r = bm + wm * 32 + mt * 16 + rr * 8 + g;
            if (r < M) {
                int s = 0, d = 0;
                if (EDGE) { s = src[r]; d = dst[r]; }
#pragma unroll
                for (int nt = 0; nt < 8; nt++) {
                    const int col = bn + wn * 64 + nt * 8 + tg * 2;
                    float2 o = make_float2(acc[mt][nt][rr * 2], acc[mt][nt][rr * 2 + 1]);
                    if (EDGE) {
                        float2 gs = __half22float2(*(const __half2*)(G0 + (size_t)s * 256 + col));
                        float2 gd = __half22float2(*(const __half2*)(G1 + (size_t)d * 256 + col));
                        o.x += gs.x + gd.x;
                        o.y += gs.y + gd.y;
                    }
                    if (HALFOUT) {
                        *(__half2*)((__half*)Cv + (size_t)r * 256 + col) =
                            __floats2half2_rn(o.x, o.y);
                    } else {
                        *(float2*)((float*)Cv + (size_t)r * 256 + col) = o;
                    }
                }
            }
        }
    }
}

// batched node GEMM: blockIdx.z in [0,5): z<4 -> fp16 table, z==4 -> fp32 htmp
struct NodeGemmParams { const float* W[5]; };

__global__ __launch_bounds__(256)
void tgemm_node(const float* __restrict__ A, NodeGemmParams p,
                __half* __restrict__ hwh, float* __restrict__ htmp, int M) {
    const int z = blockIdx.z;
    if (z < 4)
        gemm_body<false, true>(A, p.W[z], hwh + (size_t)z * NFC, M,
                               nullptr, nullptr, nullptr, nullptr);
    else
        gemm_body<false, false>(A, p.W[4], htmp, M,
                                nullptr, nullptr, nullptr, nullptr);
}

__global__ __launch_bounds__(256)
void tgemm_edge(const float* __restrict__ A, const float* __restrict__ W,
                float* __restrict__ C, int M,
                const __half* __restrict__ G0, const __half* __restrict__ G1,
                const int* __restrict__ src, const int* __restrict__ dst) {
    gemm_body<true, false>(A, W, C, M, G0, G1, src, dst);
}

// ---------------- CSR build --------------------------------------------------
__global__ void k_zero_deg(int* __restrict__ df, int* __restrict__ db) {
    int i = blockIdx.x * blockDim.x + threadIdx.x;
    if (i < NNODE) { df[i] = 0; db[i] = 0; }
}
__global__ void k_count(const int* __restrict__ src, const int* __restrict__ dst,
                        int* __restrict__ degf, int* __restrict__ degb) {
    int e = blockIdx.x * blockDim.x + threadIdx.x;
    if (e >= NEDGE) return;
    atomicAdd(&degf[dst[e]], 1);
    atomicAdd(&degb[src[e]], 1);
}
__device__ void scan_one(const int* __restrict__ deg, int* __restrict__ rp,
                         int* __restrict__ cur, int* sm) {
    const int t  = threadIdx.x;
    const int CH = (NNODE + 1023) / 1024;
    int lo = t * CH;
    int hi = lo + CH; if (hi > NNODE) hi = NNODE;
    int s = 0;
    for (int i = lo; i < hi; i++) s += deg[i];
    sm[t] = s;
    __syncthreads();
    for (int off = 1; off < 1024; off <<= 1) {
        int v = (t >= off) ? sm[t - off] : 0;
        __syncthreads();
        sm[t] += v;
        __syncthreads();
    }
    int run = (t == 0) ? 0 : sm[t - 1];
    for (int i = lo; i < hi; i++) { rp[i] = run; cur[i] = run; run += deg[i]; }
    if (t == 1023) rp[NNODE] = run;
    __syncthreads();
}
__global__ void k_scan(const int* degf, const int* degb,
                       int* rpf, int* rpb, int* curf, int* curb) {
    __shared__ int sm[1024];
    scan_one(degf, rpf, curf, sm);
    scan_one(degb, rpb, curb, sm);
}
__global__ void k_fill(const int* __restrict__ src, const int* __restrict__ dst,
                       int* __restrict__ curf, int* __restrict__ curb,
                       int* __restrict__ eidf, int* __restrict__ eidb) {
    int e = blockIdx.x * blockDim.x + threadIdx.x;
    if (e >= NEDGE) return;
    int p = atomicAdd(&curf[dst[e]], 1);
    eidf[p] = e;
    int q = atomicAdd(&curb[src[e]], 1);
    eidb[q] = e;
}

// ---------------- fused edge colstats + attention logits ---------------------
__global__ __launch_bounds__(256)
void k_estats(const float* __restrict__ X,
              const float* __restrict__ af, const float* __restrict__ ab,
              float* __restrict__ lf, float* __restrict__ lb,
              float* __restrict__ sum, float* __restrict__ ssq) {
    __shared__ float s_s[256], s_q[256];
    const int tid = threadIdx.x, lane = tid & 31, warp = tid >> 5;
    s_s[tid] = 0.f; s_q[tid] = 0.f;
    __syncthreads();

    const float4* af4 = (const float4*)af;
    const float4* ab4 = (const float4*)ab;
    const float4 fa0 = af4[lane], fa1 = af4[lane + 32];
    const float4 ba0 = ab4[lane], ba1 = ab4[lane + 32];

    float cs[8] = {0}, cq[8] = {0};

    long w  = (long)blockIdx.x * 8 + warp;
    long nw = (long)gridDim.x * 8;
    for (long r = w; r < NEDGE; r += nw) {
        const float4* row = (const float4*)(X + r * 256);
        float4 v0 = row[lane], v1 = row[lane + 32];
        cs[0] += v0.x; cs[1] += v0.y; cs[2] += v0.z; cs[3] += v0.w;
        cs[4] += v1.x; cs[5] += v1.y; cs[6] += v1.z; cs[7] += v1.w;
        cq[0] += v0.x * v0.x; cq[1] += v0.y * v0.y; cq[2] += v0.z * v0.z; cq[3] += v0.w * v0.w;
        cq[4] += v1.x * v1.x; cq[5] += v1.y * v1.y; cq[6] += v1.z * v1.z; cq[7] += v1.w * v1.w;
        float df = v0.x * fa0.x + v0.y * fa0.y + v0.z * fa0.z + v0.w * fa0.w
                 + v1.x * fa1.x + v1.y * fa1.y + v1.z * fa1.z + v1.w * fa1.w;
        float db = v0.x * ba0.x + v0.y * ba0.y + v0.z * ba0.z + v0.w * ba0.w
                 + v1.x * ba1.x + v1.y * ba1.y + v1.z * ba1.z + v1.w * ba1.w;
#pragma unroll
        for (int o = 16; o > 0; o >>= 1) {
            df += __shfl_xor_sync(0xffffffffu, df, o);
            db += __shfl_xor_sync(0xffffffffu, db, o);
        }
        if (lane == 0) {
            lf[r] = df > 0.f ? df : 0.2f * df;
            lb[r] = db > 0.f ? db : 0.2f * db;
        }
    }
#pragma unroll
    for (int k = 0; k < 4; k++) {
        atomicAdd(&s_s[lane * 4 + k], cs[k]);
        atomicAdd(&s_s[128 + lane * 4 + k], cs[4 + k]);
        atomicAdd(&s_q[lane * 4 + k], cq[k]);
        atomicAdd(&s_q[128 + lane * 4 + k], cq[4 + k]);
    }
    __syncthreads();
    atomicAdd(&sum[tid], s_s[tid]);
    atomicAdd(&ssq[tid], s_q[tid]);
}

// ---------------- BN stats (node-side) ---------------------------------------
__global__ void k_zero_stats(float* __restrict__ sum, float* __restrict__ ssq) {
    int c = threadIdx.x;
    sum[c] = 0.f;
    ssq[c] = 0.f;
}
__global__ void k_colstats(const float* __restrict__ X, int M,
                           float* __restrict__ sum, float* __restrict__ ssq) {
    int c = threadIdx.x;
    long chunk = ((long)M + gridDim.x - 1) / gridDim.x;
    long r0 = (long)blockIdx.x * chunk;
    long r1 = r0 + chunk;
    if (r1 > M) r1 = M;
    float s = 0.f, q = 0.f;
    for (long r = r0; r < r1; r++) {
        float v = X[r * FDIM + c];
        s += v; q += v * v;
    }
    atomicAdd(&sum[c], s);
    atomicAdd(&ssq[c], q);
}
__global__ void k_bnfin(const float* __restrict__ sum, const float* __restrict__ ssq,
                        int M, float* __restrict__ mean, float* __restrict__ rstd) {
    int c = threadIdx.x;
    float mu  = sum[c] / (float)M;
    float var = ssq[c] / (float)M - mu * mu;
    mean[c] = mu;
    rstd[c] = rsqrtf(var + 1e-5f);
}

// ---------------- residual + BN + relu ---------------------------------------
__global__ void k_bnres(float4* __restrict__ out, const float4* __restrict__ in,
                        const float4* __restrict__ tmp,
                        const float4* __restrict__ mean, const float4* __restrict__ rstd,
                        const float4* __restrict__ gam, const float4* __restrict__ bet,
                        long n4) {
    long i = (long)blockIdx.x * blockDim.x + threadIdx.x;
    if (i >= n4) return;
    int c = (int)(i & 63);
    float4 t = tmp[i], v = in[i];
    float4 m = mean[c], r = rstd[c], g = gam[c], b = bet[c];
    float x;
    x = (t.x - m.x) * r.x * g.x + b.x; v.x += x > 0.f ? x : 0.f;
    x = (t.y - m.y) * r.y * g.y + b.y; v.y += x > 0.f ? x : 0.f;
    x = (t.z - m.z) * r.z * g.z + b.z; v.z += x > 0.f ? x : 0.f;
    x = (t.w - m.w) * r.w * g.w + b.w; v.w += x > 0.f ? x : 0.f;
    out[i] = v;
}

// ---------------- per-node softmax + aggregation (CSR gather, no atomics) ----
__device__ __forceinline__ float bred(float v, float* s, bool ismax) {
    const int lane = threadIdx.x & 31, warp = threadIdx.x >> 5;
#pragma unroll
    for (int o = 16; o > 0; o >>= 1) {
        float t = __shfl_xor_sync(0xffffffffu, v, o);
        v = ismax ? fmaxf(v, t) : v + t;
    }
    if (lane == 0) s[warp] = v;
    __syncthreads();
    if (threadIdx.x == 0) {
        float r = s[0];
#pragma unroll
        for (int i = 1; i < 8; i++) r = ismax ? fmaxf(r, s[i]) : r + s[i];
        s[0] = r;
    }
    __syncthreads();
    float r = s[0];
    __syncthreads();
    return r;
}

#define DEG_CAP 1024

__device__ float agg_one(int n, const int* __restrict__ rp, const int* __restrict__ eid,
                         const int* __restrict__ oth, const float* __restrict__ lg,
                         const __half* __restrict__ feat,
                         int* s_i, float* s_a, float* s_red) {
    const int tid = threadIdx.x;
    const int beg = rp[n], end = rp[n + 1];
    const int deg = end - beg;
    if (deg == 0) return 0.f;
    const bool c = (deg <= DEG_CAP);

    float m = -3.4e38f;
    for (int j = tid; j < deg; j += 256) {
        int e = __ldg(&eid[beg + j]);
        float l = __ldg(&lg[e]);
        if (c) { s_i[j] = e; s_a[j] = l; }
        m = fmaxf(m, l);
    }
    m = bred(m, s_red, true);

    float den = 0.f;
    for (int j = tid; j < deg; j += 256) {
        int e = c ? s_i[j] : __ldg(&eid[beg + j]);
        float l = c ? s_a[j] : __ldg(&lg[e]);
        float ex = __expf(l - m);
        int o = __ldg(&oth[e]);
        if (c) { s_a[j] = ex; s_i[j] = o; }
        den += ex;
    }
    den = bred(den, s_red, false);
    const float rden = 1.f / (den + 1e-9f);

    float a0 = 0.f, a1 = 0.f, a2 = 0.f, a3 = 0.f;
    if (c) {
        int j = 0;
        for (; j + 4 <= deg; j += 4) {
            a0 = fmaf(s_a[j + 0], __half2float(feat[(size_t)s_i[j + 0] * 256 + tid]), a0);
            a1 = fmaf(s_a[j + 1], __half2float(feat[(size_t)s_i[j + 1] * 256 + tid]), a1);
            a2 = fmaf(s_a[j + 2], __half2float(feat[(size_t)s_i[j + 2] * 256 + tid]), a2);
            a3 = fmaf(s_a[j + 3], __half2float(feat[(size_t)s_i[j + 3] * 256 + tid]), a3);
        }
        for (; j < deg; j++)
            a0 = fmaf(s_a[j], __half2float(feat[(size_t)s_i[j] * 256 + tid]), a0);
    } else {
        for (int j = 0; j < deg; j++) {
            int e = __ldg(&eid[beg + j]);
            float ex = __expf(__ldg(&lg[e]) - m);
            int o = __ldg(&oth[e]);
            a0 = fmaf(ex, __half2float(feat[(size_t)o * 256 + tid]), a0);
        }
    }
    return ((a0 + a1) + (a2 + a3)) * rden;
}

__global__ __launch_bounds__(256)
void k_node_agg(const int* __restrict__ rpf, const int* __restrict__ eidf,
                const int* __restrict__ src,
                const int* __restrict__ rpb, const int* __restrict__ eidb,
                const int* __restrict__ dst,
                const float* __restrict__ lf, const float* __restrict__ lb,
                const __half* __restrict__ hwf, const __half* __restrict__ hwb,
                float* __restrict__ htmp) {
    __shared__ int   s_i[DEG_CAP];
    __shared__ float s_a[DEG_CAP];
    __shared__ float s_red[8];
    const int n = blockIdx.x;
    float acc = agg_one(n, rpf, eidf, src, lf, hwf, s_i, s_a, s_red);
    __syncthreads();
    acc += agg_one(n, rpb, eidb, dst, lb, hwb, s_i, s_a, s_red);
    htmp[(size_t)n * 256 + threadIdx.x] += acc;
}

// ---------------- launcher ---------------------------------------------------
extern "C" void kernel_launch(void* const* d_in, const int* in_sizes, int n_in,
                              void* d_out, int out_size) {
    const float* in_h   = (const float*)d_in[0];
    const float* in_e   = (const float*)d_in[1];
    const int*   src    = (const int*)d_in[2];
    const int*   dst    = (const int*)d_in[3];
    const float* We     = (const float*)d_in[4];
    const float* Ws     = (const float*)d_in[5];
    const float* Wd     = (const float*)d_in[6];
    const float* Wself  = (const float*)d_in[7];
    const float* Wf     = (const float*)d_in[8];
    const float* Wb     = (const float*)d_in[9];
    const float* att_f  = (const float*)d_in[10];
    const float* att_b  = (const float*)d_in[11];
    const float* ge     = (const float*)d_in[12];
    const float* be     = (const float*)d_in[13];
    const float* gh     = (const float*)d_in[14];
    const float* bh     = (const float*)d_in[15];

    float* h_out = (float*)d_out;
    float* e_out = (float*)d_out + (size_t)NNODE * FDIM;

    float *etmp, *htmp, *logf, *logb, *sum, *ssq, *mean, *rstd;
    __half *hwh;
    int *degf, *degb, *rpf, *rpb, *curf, *curb, *eidf, *eidb;
    cudaGetSymbolAddress((void**)&etmp, g_etmp);
    cudaGetSymbolAddress((void**)&hwh,  g_hwh);
    cudaGetSymbolAddress((void**)&htmp, g_htmp);
    cudaGetSymbolAddress((void**)&logf, g_logf);
    cudaGetSymbolAddress((void**)&logb, g_logb);
    cudaGetSymbolAddress((void**)&degf, g_degf);
    cudaGetSymbolAddress((void**)&degb, g_degb);
    cudaGetSymbolAddress((void**)&rpf,  g_rpf);
    cudaGetSymbolAddress((void**)&rpb,  g_rpb);
    cudaGetSymbolAddress((void**)&curf, g_curf);
    cudaGetSymbolAddress((void**)&curb, g_curb);
    cudaGetSymbolAddress((void**)&eidf, g_eidf);
    cudaGetSymbolAddress((void**)&eidb, g_eidb);
    cudaGetSymbolAddress((void**)&sum,  g_sum);
    cudaGetSymbolAddress((void**)&ssq,  g_ssq);
    cudaGetSymbolAddress((void**)&mean, g_mean);
    cudaGetSymbolAddress((void**)&rstd, g_rstd);

    __half* hwsh = hwh + 0 * NFC;
    __half* hwdh = hwh + 1 * NFC;
    __half* hwfh = hwh + 2 * NFC;
    __half* hwbh = hwh + 3 * NFC;

    // ---- CSR build (once per launch; graph is static across layers) ----
    k_zero_deg<<<(NNODE + 255) / 256, 256>>>(degf, degb);
    k_count<<<(NEDGE + 255) / 256, 256>>>(src, dst, degf, degb);
    k_scan<<<1, 1024>>>(degf, degb, rpf, rpb, curf, curb);
    k_fill<<<(NEDGE + 255) / 256, 256>>>(src, dst, curf, curb, eidf, eidb);

    dim3 gN((NNODE + BM - 1) / BM, 2, 5);
    dim3 gE(NEDGE / BM, 2);

    for (int l = 0; l < NL; l++) {
        const float* h_in = (l == 0) ? in_h : h_out;
        const float* e_in = (l == 0) ? in_e : e_out;
        size_t WO = (size_t)l * FDIM * FDIM;
        size_t VO = (size_t)l * FDIM;

        NodeGemmParams p;
        p.W[0] = Ws + WO;
        p.W[1] = Wd + WO;
        p.W[2] = Wf + WO;
        p.W[3] = Wb + WO;
        p.W[4] = Wself + WO;
        tgemm_node<<<gN, 256>>>(h_in, p, hwh, htmp, NNODE);

        tgemm_edge<<<gE, 256>>>(e_in, We + WO, etmp, NEDGE, hwsh, hwdh, src, dst);

        // fused edge BN stats + attention logits (one pass over etmp)
        k_zero_stats<<<1, 256>>>(sum, ssq);
        k_estats<<<1024, 256>>>(etmp, att_f + VO, att_b + VO, logf, logb, sum, ssq);
        k_bnfin<<<1, 256>>>(sum, ssq, NEDGE, mean, rstd);

        // e_new = e + relu(bn(e_tmp))
        k_bnres<<<(int)(((long)NEDGE * 64 + 255) / 256), 256>>>(
            (float4*)e_out, (const float4*)e_in, (const float4*)etmp,
            (const float4*)mean, (const float4*)rstd,
            (const float4*)(ge + VO), (const float4*)(be + VO), (long)NEDGE * 64);

        // per-node softmax + aggregation (both directions), no atomics
        k_node_agg<<<NNODE, 256>>>(rpf, eidf, src, rpb, eidb, dst,
                                   logf, logb, hwfh, hwbh, htmp);

        // node BN + residual
        k_zero_stats<<<1, 256>>>(sum, ssq);
        k_colstats<<<256, 256>>>(htmp, NNODE, sum, ssq);
        k_bnfin<<<1, 256>>>(sum, ssq, NNODE, mean, rstd);
        k_bnres<<<(int)(((long)NNODE * 64 + 255) / 256), 256>>>(
            (float4*)h_out, (const float4*)h_in, (const float4*)htmp,
            (const float4*)mean, (const float4*)rstd,
            (const float4*)(gh + VO), (const float4*)(bh + VO), (long)NNODE * 64);
    }
}

// round 11
// speedup vs baseline: 2.1314x; 1.0712x over previous
#include <cuda_runtime.h>
#include <cuda_fp16.h>

#define NL 4
#define NNODE 50000
#define NEDGE 800000
#define FDIM 256
#define NFC ((size_t)NNODE * FDIM)

// ---------------- scratch (static device globals; no allocation allowed) ----
__device__ __half   g_etmph[(size_t)NEDGE * FDIM];      // e_tmp  [E,F] fp16
__device__ __half   g_eh[(size_t)NEDGE * FDIM];         // fp16 shadow of e (GEMM A)
__device__ __half   g_hwh[(size_t)4 * NNODE * FDIM];    // hWs,hWd,hWf,hWb (fp16)
__device__ float    g_htmp[(size_t)NNODE * FDIM];       // h@Wself + agg (fp32)
__device__ float    g_logf[NEDGE];
__device__ float    g_logb[NEDGE];
__device__ int      g_degf[NNODE], g_degb[NNODE];
__device__ int      g_rpf[NNODE + 1], g_rpb[NNODE + 1];
__device__ int      g_curf[NNODE], g_curb[NNODE];
__device__ int      g_eidf[NEDGE], g_eidb[NEDGE];
__device__ float    g_sum[FDIM], g_ssq[FDIM], g_mean[FDIM], g_rstd[FDIM];

// ---------------- helpers ----------------------------------------------------
__device__ __forceinline__ void mma16(float* c, const unsigned* a, const unsigned* b) {
    asm volatile(
        "mma.sync.aligned.m16n8k16.row.col.f32.f16.f16.f32 "
        "{%0,%1,%2,%3}, {%4,%5,%6,%7}, {%8,%9}, {%0,%1,%2,%3};"
        : "+f"(c[0]), "+f"(c[1]), "+f"(c[2]), "+f"(c[3])
        : "r"(a[0]), "r"(a[1]), "r"(a[2]), "r"(a[3]), "r"(b[0]), "r"(b[1]));
}
__device__ __forceinline__ void ldsm4(unsigned& r0, unsigned& r1, unsigned& r2, unsigned& r3,
                                      unsigned a) {
    asm volatile("ldmatrix.sync.aligned.m8n8.x4.shared.b16 {%0,%1,%2,%3}, [%4];"
                 : "=r"(r0), "=r"(r1), "=r"(r2), "=r"(r3) : "r"(a));
}
__device__ __forceinline__ void ldsm4t(unsigned& r0, unsigned& r1, unsigned& r2, unsigned& r3,
                                       unsigned a) {
    asm volatile("ldmatrix.sync.aligned.m8n8.x4.trans.shared.b16 {%0,%1,%2,%3}, [%4];"
                 : "=r"(r0), "=r"(r1), "=r"(r2), "=r"(r3) : "r"(a));
}
__device__ __forceinline__ uint4 pack8h(float4 a, float4 b) {
    __half2 h0 = __floats2half2_rn(a.x, a.y);
    __half2 h1 = __floats2half2_rn(a.z, a.w);
    __half2 h2 = __floats2half2_rn(b.x, b.y);
    __half2 h3 = __floats2half2_rn(b.z, b.w);
    uint4 u;
    u.x = *(unsigned*)&h0; u.y = *(unsigned*)&h1;
    u.z = *(unsigned*)&h2; u.w = *(unsigned*)&h3;
    return u;
}

// ---------------- FP16 tensor-core GEMM body ---------------------------------
// C[M,256] = A[M,256] @ W[256,256]
// AHALF: A already fp16 (direct 16B copy into smem)
// EDGE : epilogue adds fp16-table gathers G0[src], G1[dst]
// HALFOUT: epilogue writes fp16
#define BM 128
#define BK 16
#define APADH 24
#define BPADH 136

template <bool EDGE, bool HALFOUT, bool AHALF>
__device__ __forceinline__ void gemm_body(
    const void* __restrict__ Av, const float* __restrict__ W,
    void* __restrict__ Cv, int M,
    const __half* __restrict__ G0, const __half* __restrict__ G1,
    const int* __restrict__ src, const int* __restrict__ dst)
{
    __shared__ __align__(16) __half As[2][BM][APADH];
    __shared__ __align__(16) __half Bs[2][BK][BPADH];

    const int tid  = threadIdx.x;
    const int warp = tid >> 5;
    const int lane = tid & 31;
    const int wm   = warp & 3;
    const int wn   = warp >> 2;
    const int bm   = blockIdx.x * BM;
    const int bn   = blockIdx.y * 128;
    const int g    = lane >> 2;
    const int tg   = lane & 3;

    const int ar = tid >> 1;
    const int ak = (tid & 1) * 8;
    const int bk = tid >> 4;
    const int bq = (tid & 15) * 8;

    float acc[2][8][4];
#pragma unroll
    for (int i = 0; i < 2; i++)
#pragma unroll
        for (int j = 0; j < 8; j++)
#pragma unroll
            for (int q = 0; q < 4; q++) acc[i][j][q] = 0.f;

    float4 a0v, a1v, b0v, b1v;
    uint4 au4;

    auto gload = [&](int k0) {
        const int row = bm + ar;
        if (AHALF) {
            au4 = *(const uint4*)((const __half*)Av + (size_t)row * 256 + k0 + ak);
        } else {
            const float4 z = make_float4(0.f, 0.f, 0.f, 0.f);
            if (row < M) {
                a0v = *(const float4*)((const float*)Av + (size_t)row * 256 + k0 + ak);
                a1v = *(const float4*)((const float*)Av + (size_t)row * 256 + k0 + ak + 4);
            } else { a0v = z; a1v = z; }
        }
        b0v = *(const float4*)(W + (size_t)(k0 + bk) * 256 + bn + bq);
        b1v = *(const float4*)(W + (size_t)(k0 + bk) * 256 + bn + bq + 4);
    };
    auto sstore = [&](int s) {
        if (AHALF)
            *(uint4*)(&As[s][ar][ak]) = au4;
        else
            *(uint4*)(&As[s][ar][ak]) = pack8h(a0v, a1v);
        *(uint4*)(&Bs[s][bk][bq]) = pack8h(b0v, b1v);
    };

    gload(0);
    sstore(0);
    __syncthreads();

#pragma unroll 2
    for (int kt = 0; kt < 16; kt++) {
        const int cur = kt & 1;
        if (kt < 15) gload((kt + 1) * BK);

        unsigned af[2][4];
#pragma unroll
        for (int mt = 0; mt < 2; mt++) {
            unsigned sa = (unsigned)__cvta_generic_to_shared(
                &As[cur][wm * 32 + mt * 16 + (lane & 15)][(lane >> 4) * 8]);
            ldsm4(af[mt][0], af[mt][1], af[mt][2], af[mt][3], sa);
        }
        unsigned bf[8][2];
#pragma unroll
        for (int j = 0; j < 4; j++) {
            unsigned sb = (unsigned)__cvta_generic_to_shared(
                &Bs[cur][lane & 15][wn * 64 + j * 16 + (lane >> 4) * 8]);
            unsigned t0, t1, t2, t3;
            ldsm4t(t0, t1, t2, t3, sb);
            bf[2 * j][0] = t0; bf[2 * j][1] = t1;
            bf[2 * j + 1][0] = t2; bf[2 * j + 1][1] = t3;
        }
#pragma unroll
        for (int mt = 0; mt < 2; mt++)
#pragma unroll
            for (int nt = 0; nt < 8; nt++)
                mma16(acc[mt][nt], af[mt], bf[nt]);

        if (kt < 15) sstore((kt + 1) & 1);
        __syncthreads();
    }

#pragma unroll
    for (int mt = 0; mt < 2; mt++) {
#pragma unroll
        for (int rr = 0; rr < 2; rr++) {
            const int r = bm + wm * 32 + mt * 16 + rr * 8 + g;
            if (r < M) {
                int s = 0, d = 0;
                if (EDGE) { s = src[r]; d = dst[r]; }
#pragma unroll
                for (int nt = 0; nt < 8; nt++) {
                    const int col = bn + wn * 64 + nt * 8 + tg * 2;
                    float2 o = make_float2(acc[mt][nt][rr * 2], acc[mt][nt][rr * 2 + 1]);
                    if (EDGE) {
                        float2 gs = __half22float2(*(const __half2*)(G0 + (size_t)s * 256 + col));
                        float2 gd = __half22float2(*(const __half2*)(G1 + (size_t)d * 256 + col));
                        o.x += gs.x + gd.x;
                        o.y += gs.y + gd.y;
                    }
                    if (HALFOUT) {
                        *(__half2*)((__half*)Cv + (size_t)r * 256 + col) =
                            __floats2half2_rn(o.x, o.y);
                    } else {
                        *(float2*)((float*)Cv + (size_t)r * 256 + col) = o;
                    }
                }
            }
        }
    }
}

// batched node GEMM: blockIdx.z in [0,5): z<4 -> fp16 table, z==4 -> fp32 htmp
struct NodeGemmParams { const float* W[5]; };

__global__ __launch_bounds__(256)
void tgemm_node(const float* __restrict__ A, NodeGemmParams p,
                __half* __restrict__ hwh, float* __restrict__ htmp, int M) {
    const int z = blockIdx.z;
    if (z < 4)
        gemm_body<false, true, false>(A, p.W[z], hwh + (size_t)z * NFC, M,
                                      nullptr, nullptr, nullptr, nullptr);
    else
        gemm_body<false, false, false>(A, p.W[4], htmp, M,
                                       nullptr, nullptr, nullptr, nullptr);
}

__global__ __launch_bounds__(256)
void tgemm_edge(const __half* __restrict__ A, const float* __restrict__ W,
                __half* __restrict__ C, int M,
                const __half* __restrict__ G0, const __half* __restrict__ G1,
                const int* __restrict__ src, const int* __restrict__ dst) {
    gemm_body<true, true, true>(A, W, C, M, G0, G1, src, dst);
}

// ---------------- CSR build --------------------------------------------------
__global__ void k_zero_deg(int* __restrict__ df, int* __restrict__ db) {
    int i = blockIdx.x * blockDim.x + threadIdx.x;
    if (i < NNODE) { df[i] = 0; db[i] = 0; }
}
__global__ void k_count(const int* __restrict__ src, const int* __restrict__ dst,
                        int* __restrict__ degf, int* __restrict__ degb) {
    int e = blockIdx.x * blockDim.x + threadIdx.x;
    if (e >= NEDGE) return;
    atomicAdd(&degf[dst[e]], 1);
    atomicAdd(&degb[src[e]], 1);
}
__device__ void scan_one(const int* __restrict__ deg, int* __restrict__ rp,
                         int* __restrict__ cur, int* sm) {
    const int t  = threadIdx.x;
    const int CH = (NNODE + 1023) / 1024;
    int lo = t * CH;
    int hi = lo + CH; if (hi > NNODE) hi = NNODE;
    int s = 0;
    for (int i = lo; i < hi; i++) s += deg[i];
    sm[t] = s;
    __syncthreads();
    for (int off = 1; off < 1024; off <<= 1) {
        int v = (t >= off) ? sm[t - off] : 0;
        __syncthreads();
        sm[t] += v;
        __syncthreads();
    }
    int run = (t == 0) ? 0 : sm[t - 1];
    for (int i = lo; i < hi; i++) { rp[i] = run; cur[i] = run; run += deg[i]; }
    if (t == 1023) rp[NNODE] = run;
    __syncthreads();
}
__global__ void k_scan(const int* degf, const int* degb,
                       int* rpf, int* rpb, int* curf, int* curb) {
    __shared__ int sm[1024];
    scan_one(degf, rpf, curf, sm);
    scan_one(degb, rpb, curb, sm);
}
__global__ void k_fill(const int* __restrict__ src, const int* __restrict__ dst,
                       int* __restrict__ curf, int* __restrict__ curb,
                       int* __restrict__ eidf, int* __restrict__ eidb) {
    int e = blockIdx.x * blockDim.x + threadIdx.x;
    if (e >= NEDGE) return;
    int p = atomicAdd(&curf[dst[e]], 1);
    eidf[p] = e;
    int q = atomicAdd(&curb[src[e]], 1);
    eidb[q] = e;
}

// ---------------- fp32 -> fp16 convert (once, for e shadow) ------------------
__global__ void k_f2h(const float4* __restrict__ in, __half* __restrict__ out, long n4) {
    long i = (long)blockIdx.x * blockDim.x + threadIdx.x;
    if (i >= n4) return;
    float4 v = in[i];
    *(uint2*)(out + i * 4) = make_uint2(
        *(unsigned*)&(__half2&)*(__half2[]){__floats2half2_rn(v.x, v.y)},
        *(unsigned*)&(__half2&)*(__half2[]){__floats2half2_rn(v.z, v.w)});
}

// ---------------- fused edge colstats + attention logits (fp16 input) --------
__global__ __launch_bounds__(256)
void k_estats_h(const __half* __restrict__ X,
                const float* __restrict__ af, const float* __restrict__ ab,
                float* __restrict__ lf, float* __restrict__ lb,
                float* __restrict__ sum, float* __restrict__ ssq) {
    __shared__ float s_s[256], s_q[256];
    const int tid = threadIdx.x, lane = tid & 31, warp = tid >> 5;
    s_s[tid] = 0.f; s_q[tid] = 0.f;
    __syncthreads();

    // lane owns columns [lane*8, lane*8+8)
    float fa[8], ba[8];
    *(float4*)(fa)     = *(const float4*)(af + lane * 8);
    *(float4*)(fa + 4) = *(const float4*)(af + lane * 8 + 4);
    *(float4*)(ba)     = *(const float4*)(ab + lane * 8);
    *(float4*)(ba + 4) = *(const float4*)(ab + lane * 8 + 4);

    float cs[8] = {0}, cq[8] = {0};

    long w  = (long)blockIdx.x * 8 + warp;
    long nw = (long)gridDim.x * 8;
    for (long r = w; r < NEDGE; r += nw) {
        uint4 u = *(const uint4*)(X + r * 256 + lane * 8);
        __half2* hp = (__half2*)&u;
        float v[8];
        float2 f;
        f = __half22float2(hp[0]); v[0] = f.x; v[1] = f.y;
        f = __half22float2(hp[1]); v[2] = f.x; v[3] = f.y;
        f = __half22float2(hp[2]); v[4] = f.x; v[5] = f.y;
        f = __half22float2(hp[3]); v[6] = f.x; v[7] = f.y;
        float df = 0.f, db = 0.f;
#pragma unroll
        for (int k = 0; k < 8; k++) {
            cs[k] += v[k];
            cq[k] += v[k] * v[k];
            df = fmaf(v[k], fa[k], df);
            db = fmaf(v[k], ba[k], db);
        }
#pragma unroll
        for (int o = 16; o > 0; o >>= 1) {
            df += __shfl_xor_sync(0xffffffffu, df, o);
            db += __shfl_xor_sync(0xffffffffu, db, o);
        }
        if (lane == 0) {
            lf[r] = df > 0.f ? df : 0.2f * df;
            lb[r] = db > 0.f ? db : 0.2f * db;
        }
    }
#pragma unroll
    for (int k = 0; k < 8; k++) {
        atomicAdd(&s_s[lane * 8 + k], cs[k]);
        atomicAdd(&s_q[lane * 8 + k], cq[k]);
    }
    __syncthreads();
    atomicAdd(&sum[tid], s_s[tid]);
    atomicAdd(&ssq[tid], s_q[tid]);
}

// ---------------- BN stats (node-side) ---------------------------------------
__global__ void k_zero_stats(float* __restrict__ sum, float* __restrict__ ssq) {
    int c = threadIdx.x;
    sum[c] = 0.f;
    ssq[c] = 0.f;
}
__global__ void k_colstats(const float* __restrict__ X, int M,
                           float* __restrict__ sum, float* __restrict__ ssq) {
    int c = threadIdx.x;
    long chunk = ((long)M + gridDim.x - 1) / gridDim.x;
    long r0 = (long)blockIdx.x * chunk;
    long r1 = r0 + chunk;
    if (r1 > M) r1 = M;
    float s = 0.f, q = 0.f;
    for (long r = r0; r < r1; r++) {
        float v = X[r * FDIM + c];
        s += v; q += v * v;
    }
    atomicAdd(&sum[c], s);
    atomicAdd(&ssq[c], q);
}
__global__ void k_bnfin(const float* __restrict__ sum, const float* __restrict__ ssq,
                        int M, float* __restrict__ mean, float* __restrict__ rstd) {
    int c = threadIdx.x;
    float mu  = sum[c] / (float)M;
    float var = ssq[c] / (float)M - mu * mu;
    mean[c] = mu;
    rstd[c] = rsqrtf(var + 1e-5f);
}

// ---------------- residual + BN + relu (node, fp32 tmp) ----------------------
__global__ void k_bnres(float4* __restrict__ out, const float4* __restrict__ in,
                        const float4* __restrict__ tmp,
                        const float4* __restrict__ mean, const float4* __restrict__ rstd,
                        const float4* __restrict__ gam, const float4* __restrict__ bet,
                        long n4) {
    long i = (long)blockIdx.x * blockDim.x + threadIdx.x;
    if (i >= n4) return;
    int c = (int)(i & 63);
    float4 t = tmp[i], v = in[i];
    float4 m = mean[c], r = rstd[c], g = gam[c], b = bet[c];
    float x;
    x = (t.x - m.x) * r.x * g.x + b.x; v.x += x > 0.f ? x : 0.f;
    x = (t.y - m.y) * r.y * g.y + b.y; v.y += x > 0.f ? x : 0.f;
    x = (t.z - m.z) * r.z * g.z + b.z; v.z += x > 0.f ? x : 0.f;
    x = (t.w - m.w) * r.w * g.w + b.w; v.w += x > 0.f ? x : 0.f;
    out[i] = v;
}

// ---------------- residual + BN + relu (edge: fp16 tmp, dual fp32+fp16 out) --
__global__ void k_bnres_e(float4* __restrict__ outf, __half* __restrict__ outh,
                          const float4* __restrict__ in,
                          const __half* __restrict__ tmph,
                          const float4* __restrict__ mean, const float4* __restrict__ rstd,
                          const float4* __restrict__ gam, const float4* __restrict__ bet,
                          long n4) {
    long i = (long)blockIdx.x * blockDim.x + threadIdx.x;
    if (i >= n4) return;
    int c = (int)(i & 63);
    uint2 tu = *(const uint2*)(tmph + i * 4);
    float2 t01 = __half22float2(*(__half2*)&tu.x);
    float2 t23 = __half22float2(*(__half2*)&tu.y);
    float4 v = in[i];
    float4 m = mean[c], r = rstd[c], g = gam[c], b = bet[c];
    float x;
    x = (t01.x - m.x) * r.x * g.x + b.x; v.x += x > 0.f ? x : 0.f;
    x = (t01.y - m.y) * r.y * g.y + b.y; v.y += x > 0.f ? x : 0.f;
    x = (t23.x - m.z) * r.z * g.z + b.z; v.z += x > 0.f ? x : 0.f;
    x = (t23.y - m.w) * r.w * g.w + b.w; v.w += x > 0.f ? x : 0.f;
    outf[i] = v;
    __half2 h0 = __floats2half2_rn(v.x, v.y);
    __half2 h1 = __floats2half2_rn(v.z, v.w);
    *(uint2*)(outh + i * 4) = make_uint2(*(unsigned*)&h0, *(unsigned*)&h1);
}

// ---------------- per-node softmax + aggregation (CSR gather, no atomics) ----
__device__ __forceinline__ float bred(float v, float* s, bool ismax) {
    const int lane = threadIdx.x & 31, warp = threadIdx.x >> 5;
#pragma unroll
    for (int o = 16; o > 0; o >>= 1) {
        float t = __shfl_xor_sync(0xffffffffu, v, o);
        v = ismax ? fmaxf(v, t) : v + t;
    }
    if (lane == 0) s[warp] = v;
    __syncthreads();
    if (threadIdx.x == 0) {
        float r = s[0];
#pragma unroll
        for (int i = 1; i < 8; i++) r = ismax ? fmaxf(r, s[i]) : r + s[i];
        s[0] = r;
    }
    __syncthreads();
    float r = s[0];
    __syncthreads();
    return r;
}

#define DEG_CAP 1024

__device__ float agg_one(int n, const int* __restrict__ rp, const int* __restrict__ eid,
                         const int* __restrict__ oth, const float* __restrict__ lg,
                         const __half* __restrict__ feat,
                         int* s_i, float* s_a, float* s_red) {
    const int tid = threadIdx.x;
    const int beg = rp[n], end = rp[n + 1];
    const int deg = end - beg;
    if (deg == 0) return 0.f;
    const bool c = (deg <= DEG_CAP);

    float m = -3.4e38f;
    for (int j = tid; j < deg; j += 256) {
        int e = __ldg(&eid[beg + j]);
        float l = __ldg(&lg[e]);
        if (c) { s_i[j] = e; s_a[j] = l; }
        m = fmaxf(m, l);
    }
    m = bred(m, s_red, true);

    float den = 0.f;
    for (int j = tid; j < deg; j += 256) {
        int e = c ? s_i[j] : __ldg(&eid[beg + j]);
        float l = c ? s_a[j] : __ldg(&lg[e]);
        float ex = __expf(l - m);
        int o = __ldg(&oth[e]);
        if (c) { s_a[j] = ex; s_i[j] = o; }
        den += ex;
    }
    den = bred(den, s_red, false);
    const float rden = 1.f / (den + 1e-9f);

    float a0 = 0.f, a1 = 0.f, a2 = 0.f, a3 = 0.f;
    if (c) {
        int j = 0;
        for (; j + 4 <= deg; j += 4) {
            a0 = fmaf(s_a[j + 0], __half2float(feat[(size_t)s_i[j + 0] * 256 + tid]), a0);
            a1 = fmaf(s_a[j + 1], __half2float(feat[(size_t)s_i[j + 1] * 256 + tid]), a1);
            a2 = fmaf(s_a[j + 2], __half2float(feat[(size_t)s_i[j + 2] * 256 + tid]), a2);
            a3 = fmaf(s_a[j + 3], __half2float(feat[(size_t)s_i[j + 3] * 256 + tid]), a3);
        }
        for (; j < deg; j++)
            a0 = fmaf(s_a[j], __half2float(feat[(size_t)s_i[j] * 256 + tid]), a0);
    } else {
        for (int j = 0; j < deg; j++) {
            int e = __ldg(&eid[beg + j]);
            float ex = __expf(__ldg(&lg[e]) - m);
            int o = __ldg(&oth[e]);
            a0 = fmaf(ex, __half2float(feat[(size_t)o * 256 + tid]), a0);
        }
    }
    return ((a0 + a1) + (a2 + a3)) * rden;
}

__global__ __launch_bounds__(256)
void k_node_agg(const int* __restrict__ rpf, const int* __restrict__ eidf,
                const int* __restrict__ src,
                const int* __restrict__ rpb, const int* __restrict__ eidb,
                const int* __restrict__ dst,
                const float* __restrict__ lf, const float* __restrict__ lb,
                const __half* __restrict__ hwf, const __half* __restrict__ hwb,
                float* __restrict__ htmp) {
    __shared__ int   s_i[DEG_CAP];
    __shared__ float s_a[DEG_CAP];
    __shared__ float s_red[8];
    const int n = blockIdx.x;
    float acc = agg_one(n, rpf, eidf, src, lf, hwf, s_i, s_a, s_red);
    __syncthreads();
    acc += agg_one(n, rpb, eidb, dst, lb, hwb, s_i, s_a, s_red);
    htmp[(size_t)n * 256 + threadIdx.x] += acc;
}

// ---------------- launcher ---------------------------------------------------
extern "C" void kernel_launch(void* const* d_in, const int* in_sizes, int n_in,
                              void* d_out, int out_size) {
    const float* in_h   = (const float*)d_in[0];
    const float* in_e   = (const float*)d_in[1];
    const int*   src    = (const int*)d_in[2];
    const int*   dst    = (const int*)d_in[3];
    const float* We     = (const float*)d_in[4];
    const float* Ws     = (const float*)d_in[5];
    const float* Wd     = (const float*)d_in[6];
    const float* Wself  = (const float*)d_in[7];
    const float* Wf     = (const float*)d_in[8];
    const float* Wb     = (const float*)d_in[9];
    const float* att_f  = (const float*)d_in[10];
    const float* att_b  = (const float*)d_in[11];
    const float* ge     = (const float*)d_in[12];
    const float* be     = (const float*)d_in[13];
    const float* gh     = (const float*)d_in[14];
    const float* bh     = (const float*)d_in[15];

    float* h_out = (float*)d_out;
    float* e_out = (float*)d_out + (size_t)NNODE * FDIM;

    float *htmp, *logf, *logb, *sum, *ssq, *mean, *rstd;
    __half *hwh, *etmph, *eh;
    int *degf, *degb, *rpf, *rpb, *curf, *curb, *eidf, *eidb;
    cudaGetSymbolAddress((void**)&etmph, g_etmph);
    cudaGetSymbolAddress((void**)&eh,    g_eh);
    cudaGetSymbolAddress((void**)&hwh,   g_hwh);
    cudaGetSymbolAddress((void**)&htmp,  g_htmp);
    cudaGetSymbolAddress((void**)&logf,  g_logf);
    cudaGetSymbolAddress((void**)&logb,  g_logb);
    cudaGetSymbolAddress((void**)&degf,  g_degf);
    cudaGetSymbolAddress((void**)&degb,  g_degb);
    cudaGetSymbolAddress((void**)&rpf,   g_rpf);
    cudaGetSymbolAddress((void**)&rpb,   g_rpb);
    cudaGetSymbolAddress((void**)&curf,  g_curf);
    cudaGetSymbolAddress((void**)&curb,  g_curb);
    cudaGetSymbolAddress((void**)&eidf,  g_eidf);
    cudaGetSymbolAddress((void**)&eidb,  g_eidb);
    cudaGetSymbolAddress((void**)&sum,   g_sum);
    cudaGetSymbolAddress((void**)&ssq,   g_ssq);
    cudaGetSymbolAddress((void**)&mean,  g_mean);
    cudaGetSymbolAddress((void**)&rstd,  g_rstd);

    __half* hwsh = hwh + 0 * NFC;
    __half* hwdh = hwh + 1 * NFC;
    __half* hwfh = hwh + 2 * NFC;
    __half* hwbh = hwh + 3 * NFC;

    // ---- CSR build (once per launch; graph is static across layers) ----
    k_zero_deg<<<(NNODE + 255) / 256, 256>>>(degf, degb);
    k_count<<<(NEDGE + 255) / 256, 256>>>(src, dst, degf, degb);
    k_scan<<<1, 1024>>>(degf, degb, rpf, rpb, curf, curb);
    k_fill<<<(NEDGE + 255) / 256, 256>>>(src, dst, curf, curb, eidf, eidb);

    // fp16 shadow of e for GEMM A operand
    k_f2h<<<(int)(((long)NEDGE * 64 + 255) / 256), 256>>>((const float4*)in_e, eh, (long)NEDGE * 64);

    dim3 gN((NNODE + BM - 1) / BM, 2, 5);
    dim3 gE(NEDGE / BM, 2);

    for (int l = 0; l < NL; l++) {
        const float* h_in = (l == 0) ? in_h : h_out;
        const float* e_in = (l == 0) ? in_e : e_out;
        size_t WO = (size_t)l * FDIM * FDIM;
        size_t VO = (size_t)l * FDIM;

        NodeGemmParams p;
        p.W[0] = Ws + WO;
        p.W[1] = Wd + WO;
        p.W[2] = Wf + WO;
        p.W[3] = Wb + WO;
        p.W[4] = Wself + WO;
        tgemm_node<<<gN, 256>>>(h_in, p, hwh, htmp, NNODE);

        tgemm_edge<<<gE, 256>>>(eh, We + WO, etmph, NEDGE, hwsh, hwdh, src, dst);

        // fused edge BN stats + attention logits (one fp16 pass over etmp)
        k_zero_stats<<<1, 256>>>(sum, ssq);
        k_estats_h<<<1024, 256>>>(etmph, att_f + VO, att_b + VO, logf, logb, sum, ssq);
        k_bnfin<<<1, 256>>>(sum, ssq, NEDGE, mean, rstd);

        // e_new = e + relu(bn(e_tmp)) -> fp32 out + fp16 shadow
        k_bnres_e<<<(int)(((long)NEDGE * 64 + 255) / 256), 256>>>(
            (float4*)e_out, eh, (const float4*)e_in, etmph,
            (const float4*)mean, (const float4*)rstd,
            (const float4*)(ge + VO), (const float4*)(be + VO), (long)NEDGE * 64);

        // per-node softmax + aggregation (both directions), no atomics
        k_node_agg<<<NNODE, 256>>>(rpf, eidf, src, rpb, eidb, dst,
                                   logf, logb, hwfh, hwbh, htmp);

        // node BN + residual
        k_zero_stats<<<1, 256>>>(sum, ssq);
        k_colstats<<<256, 256>>>(htmp, NNODE, sum, ssq);
        k_bnfin<<<1, 256>>>(sum, ssq, NNODE, mean, rstd);
        k_bnres<<<(int)(((long)NNODE * 64 + 255) / 256), 256>>>(
            (float4*)h_out, (const float4*)h_in, (const float4*)htmp,
            (const float4*)mean, (const float4*)rstd,
            (const float4*)(gh + VO), (const float4*)(bh + VO), (long)NNODE * 64);
    }
}